// round 11
// baseline (speedup 1.0000x reference)
#include <cuda_runtime.h>
#include <math.h>
#include <stdint.h>

#define BB 8
#define NN_SEQ 1024
#define DD 1024
#define HH 16
#define DH 64
#define TT (BB * NN_SEQ)      // 8192 tokens
#define EE 4
#define MH 2048
#define LN_EPS 1e-5f

// ---------------- scratch (device globals; no allocations allowed) ----------
__device__ float g_Tr[BB * NN_SEQ * DD];
__device__ float g_S [BB * NN_SEQ * DD];
__device__ float g_Sn[BB * NN_SEQ * DD];    // tf32-rounded at write
__device__ float g_qkv[TT * 3 * DD];        // fused QKV, tf32-rounded at write
__device__ float g_y [BB * NN_SEQ * DD];    // tf32-rounded at write
__device__ float g_xs[BB * NN_SEQ * DD];
__device__ float g_xf[BB * NN_SEQ * DD];    // exact (router input)
__device__ float g_xfr[BB * NN_SEQ * DD];   // tf32-rounded copy (GEMM input)
__device__ float g_h [TT * MH];             // tf32-rounded at write
__device__ float g_gates[TT * EE];
__device__ float g_wts  [TT * EE];
__device__ int   g_list [EE * TT];
__device__ float g_lw   [EE * TT];
__device__ int   g_cnt  [EE];
__device__ float g_auxval[1];
__device__ float g_qkvb[3 * DD];
// pre-rounded weights: qw,kw,vw,ow (4 x 1M), ew1 (4 x 2M), ew2 (4 x 2M)
#define WR_Q  0
#define WR_K  (DD * DD)
#define WR_V  (2 * DD * DD)
#define WR_O  (3 * DD * DD)
#define WR_E1 (4 * DD * DD)
#define WR_E2 (4 * DD * DD + EE * MH * DD)
#define WR_TOTAL (4 * DD * DD + 2 * EE * MH * DD)
__device__ float g_wr[WR_TOTAL];

// ---------------- tf32 rounding helpers -------------------------------------
__device__ __forceinline__ uint32_t f2tf(float f) {
    uint32_t u;
    asm("cvt.rna.tf32.f32 %0, %1;" : "=r"(u) : "f"(f));
    return u;
}
__device__ __forceinline__ float tf32r(float f) {
    return __uint_as_float(f2tf(f));
}

__global__ __launch_bounds__(256) void round_tf32_kernel(
    const float* __restrict__ src, float* __restrict__ dst, int n)
{
    int base = (blockIdx.x * 256 + threadIdx.x) * 16;
#pragma unroll
    for (int j = 0; j < 4; j++) {
        int i = base + j * 4;
        if (i < n) {
            float4 v = *(const float4*)&src[i];
            v.x = tf32r(v.x); v.y = tf32r(v.y);
            v.z = tf32r(v.z); v.w = tf32r(v.w);
            *(float4*)&dst[i] = v;
        }
    }
}

__global__ __launch_bounds__(256) void concat_bias_kernel(
    const float* __restrict__ qb, const float* __restrict__ kb,
    const float* __restrict__ vb)
{
    int i = blockIdx.x * 256 + threadIdx.x;
    if (i < DD) {
        g_qkvb[i] = qb[i];
        g_qkvb[DD + i] = kb[i];
        g_qkvb[2 * DD + i] = vb[i];
    }
}

// ---------------- kernel 1: decomposition + seasonal + LN1 ------------------
__global__ __launch_bounds__(256) void decomp_ln1_kernel(
    const float* __restrict__ x, const float* __restrict__ alpha,
    const float* __restrict__ dw7, const float* __restrict__ dw25,
    const float* __restrict__ dw49,
    const float* __restrict__ n1g, const float* __restrict__ n1b)
{
    int bn = blockIdx.x;
    int b = bn / NN_SEQ, n = bn % NN_SEQ;
    int tid = threadIdx.x;

    float a0 = alpha[0], a1 = alpha[1], a2 = alpha[2];
    float mx = fmaxf(a0, fmaxf(a1, a2));
    float e0 = __expf(a0 - mx), e1 = __expf(a1 - mx), e2 = __expf(a2 - mx);
    float inv = 1.0f / (e0 + e1 + e2);
    float w0 = e0 * inv, w1 = e1 * inv, w2 = e2 * inv;

    const float* xb = x + (size_t)b * NN_SEQ * DD;
    float s_local[4];
    float sum = 0.f, sumsq = 0.f;

#pragma unroll
    for (int i = 0; i < 4; i++) {
        int d = tid + i * 256;
        float win[49];
#pragma unroll
        for (int j = 0; j < 49; j++) {
            int idx = n + j - 24;
            idx = idx < 0 ? -idx : idx;
            idx = idx >= NN_SEQ ? (2 * NN_SEQ - 2 - idx) : idx;
            win[j] = xb[(size_t)idx * DD + d];
        }
        float t7 = 0.f, t25 = 0.f, t49 = 0.f;
#pragma unroll
        for (int j = 0; j < 7; j++)  t7  += dw7 [d * 7  + j] * win[21 + j];
#pragma unroll
        for (int j = 0; j < 25; j++) t25 += dw25[d * 25 + j] * win[12 + j];
#pragma unroll
        for (int j = 0; j < 49; j++) t49 += dw49[d * 49 + j] * win[j];
        float tr = w0 * t7 + w1 * t25 + w2 * t49;
        float sv = win[24] - tr;
        g_Tr[(size_t)bn * DD + d] = tr;
        g_S [(size_t)bn * DD + d] = sv;
        s_local[i] = sv;
        sum += sv; sumsq += sv * sv;
    }

    __shared__ float sh1[256], sh2[256];
    sh1[tid] = sum; sh2[tid] = sumsq;
    __syncthreads();
    for (int o = 128; o > 0; o >>= 1) {
        if (tid < o) { sh1[tid] += sh1[tid + o]; sh2[tid] += sh2[tid + o]; }
        __syncthreads();
    }
    float mean = sh1[0] * (1.0f / DD);
    float var  = sh2[0] * (1.0f / DD) - mean * mean;
    float rstd = rsqrtf(var + LN_EPS);

#pragma unroll
    for (int i = 0; i < 4; i++) {
        int d = tid + i * 256;
        g_Sn[(size_t)bn * DD + d] =
            tf32r((s_local[i] - mean) * rstd * n1g[d] + n1b[d]);
    }
}

// ---------------- generic LN kernel (optional rounded second output) --------
__global__ __launch_bounds__(256) void ln_kernel(
    const float* __restrict__ in, const float* __restrict__ g,
    const float* __restrict__ bta, float* __restrict__ out,
    float* __restrict__ out_r)
{
    int bn = blockIdx.x;
    int tid = threadIdx.x;
    const float* row = in + (size_t)bn * DD;
    float v[4]; float sum = 0.f, sumsq = 0.f;
#pragma unroll
    for (int i = 0; i < 4; i++) {
        v[i] = row[tid + i * 256];
        sum += v[i]; sumsq += v[i] * v[i];
    }
    __shared__ float sh1[256], sh2[256];
    sh1[tid] = sum; sh2[tid] = sumsq;
    __syncthreads();
    for (int o = 128; o > 0; o >>= 1) {
        if (tid < o) { sh1[tid] += sh1[tid + o]; sh2[tid] += sh2[tid + o]; }
        __syncthreads();
    }
    float mean = sh1[0] * (1.0f / DD);
    float var  = sh2[0] * (1.0f / DD) - mean * mean;
    float rstd = rsqrtf(var + LN_EPS);
#pragma unroll
    for (int i = 0; i < 4; i++) {
        int d = tid + i * 256;
        float ov = (v[i] - mean) * rstd * g[d] + bta[d];
        out[(size_t)bn * DD + d] = ov;
        if (out_r) out_r[(size_t)bn * DD + d] = tf32r(ov);
    }
}

// ---------------- TF32 tensor-core NT GEMM, cp.async 3-stage pipeline -------
// All operands MUST be pre-rounded to tf32.
// mode 0: C = acc + bias (+ addend)            (dense, exact f32 out)
// mode 3: C = tf32r(acc + bias)                (dense, rounded out)
// mode 1: C[row] = tf32r(gelu(acc+bias)), A rows gathered via rowidx, row<cnt
// mode 2: C[rowidx[row]] += (acc + bias) * rowsw[row], row<cnt (scatter)
//
// Pipeline order per k-tile: wait_group -> __syncthreads -> prefetch (it+2)
// -> mma (it). Prefetch targets stage (it-1)%3, whose reads all completed
// before the barrier: race-free with ONE sync per tile, 64-deep prefetch.
__device__ __forceinline__ void mma_tf32(float* d, const uint32_t* a, const uint32_t* b) {
    asm volatile(
        "mma.sync.aligned.m16n8k8.row.col.f32.tf32.tf32.f32 "
        "{%0,%1,%2,%3}, {%4,%5,%6,%7}, {%8,%9}, {%0,%1,%2,%3};"
        : "+f"(d[0]), "+f"(d[1]), "+f"(d[2]), "+f"(d[3])
        : "r"(a[0]), "r"(a[1]), "r"(a[2]), "r"(a[3]),
          "r"(b[0]), "r"(b[1]));
}

__device__ __forceinline__ void cpa16(float* dst, const float* src) {
    uint32_t d = (uint32_t)__cvta_generic_to_shared(dst);
    asm volatile("cp.async.cg.shared.global [%0], [%1], 16;\n" :: "r"(d), "l"(src));
}

#define GSTG 3
#define GSMEM (GSTG * 4096 * 2 * (int)sizeof(float))   // 96 KB
__global__ __launch_bounds__(256, 2) void gemm_tf32(
    const float* __restrict__ A, const float* __restrict__ W,
    const float* __restrict__ bias, const float* __restrict__ addend,
    float* __restrict__ C, int M, int Nn, int K, int mode,
    const int* __restrict__ rowidx, const int* __restrict__ cnt_ptr,
    const float* __restrict__ rowsw)
{
    int m0 = blockIdx.y * 128, n0 = blockIdx.x * 128;
    int cval = cnt_ptr ? *cnt_ptr : M;
    if (m0 >= cval) return;

    extern __shared__ float sm[];
    float* Abuf = sm;                    // [GSTG][4096]
    float* Wbuf = sm + GSTG * 4096;      // [GSTG][4096]

    int tid = threadIdx.x;
    int lrow = tid >> 1;
    int cbase = (tid & 1) * 4;

    int arow = m0 + lrow;
    if (mode == 1 && rowidx) arow = rowidx[arow < cval ? arow : (cval - 1)];
    const float* Aptr = A + (size_t)arow * K + cbase * 4;
    const float* Wptr = W + (size_t)(n0 + lrow) * K + cbase * 4;

    int dsts[4];
#pragma unroll
    for (int j = 0; j < 4; j++)
        dsts[j] = lrow * 32 + ((cbase + j) ^ (lrow & 7)) * 4;

    int lane = tid & 31, wid = tid >> 5;
    int wm = wid >> 2, wn = wid & 3;
    int g = lane >> 2, c = lane & 3;

    float acc[4][4][4];
#pragma unroll
    for (int i = 0; i < 4; i++)
#pragma unroll
        for (int j = 0; j < 4; j++)
#pragma unroll
            for (int r = 0; r < 4; r++) acc[i][j][r] = 0.f;

    int nk = K / 32;
    // prologue: stages 0 and 1
#pragma unroll
    for (int st = 0; st < 2; st++) {
        if (st < nk) {
            int k0 = st * 32;
#pragma unroll
            for (int j = 0; j < 4; j++) {
                cpa16(Abuf + st * 4096 + dsts[j], Aptr + k0 + j * 4);
                cpa16(Wbuf + st * 4096 + dsts[j], Wptr + k0 + j * 4);
            }
            asm volatile("cp.async.commit_group;\n" ::);
        }
    }

    for (int it = 0; it < nk; it++) {
        if (it < nk - 1)
            asm volatile("cp.async.wait_group 1;\n" ::);
        else
            asm volatile("cp.async.wait_group 0;\n" ::);
        __syncthreads();

        int pf = it + 2;
        if (pf < nk) {
            int st = pf % GSTG;
            int k0 = pf * 32;
#pragma unroll
            for (int j = 0; j < 4; j++) {
                cpa16(Abuf + st * 4096 + dsts[j], Aptr + k0 + j * 4);
                cpa16(Wbuf + st * 4096 + dsts[j], Wptr + k0 + j * 4);
            }
            asm volatile("cp.async.commit_group;\n" ::);
        }

        const float* Ab = Abuf + (it % GSTG) * 4096;
        const float* Wb = Wbuf + (it % GSTG) * 4096;
#pragma unroll
        for (int s = 0; s < 4; s++) {
            int sw0 = ((2 * s) ^ g) * 4 + c;
            int sw1 = ((2 * s + 1) ^ g) * 4 + c;
            uint32_t af[4][4], bf[4][2];
#pragma unroll
            for (int mf = 0; mf < 4; mf++) {
                const float* pa = Ab + (wm * 64 + mf * 16 + g) * 32;
                af[mf][0] = __float_as_uint(pa[sw0]);
                af[mf][1] = __float_as_uint(pa[8 * 32 + sw0]);
                af[mf][2] = __float_as_uint(pa[sw1]);
                af[mf][3] = __float_as_uint(pa[8 * 32 + sw1]);
            }
#pragma unroll
            for (int nf = 0; nf < 4; nf++) {
                const float* pw = Wb + (wn * 32 + nf * 8 + g) * 32;
                bf[nf][0] = __float_as_uint(pw[sw0]);
                bf[nf][1] = __float_as_uint(pw[sw1]);
            }
#pragma unroll
            for (int mf = 0; mf < 4; mf++)
#pragma unroll
                for (int nf = 0; nf < 4; nf++)
                    mma_tf32(acc[mf][nf], af[mf], bf[nf]);
        }
    }

#pragma unroll
    for (int mf = 0; mf < 4; mf++) {
#pragma unroll
        for (int half = 0; half < 2; half++) {
            int r = m0 + wm * 64 + mf * 16 + g + half * 8;
#pragma unroll
            for (int nf = 0; nf < 4; nf++) {
                int col = n0 + wn * 32 + nf * 8 + 2 * c;
                float v0 = acc[mf][nf][half * 2 + 0];
                float v1 = acc[mf][nf][half * 2 + 1];
                if (bias) { v0 += bias[col]; v1 += bias[col + 1]; }
                if (mode == 0 || mode == 3) {
                    size_t off = (size_t)r * Nn + col;
                    if (addend) {
                        float2 ad = *(const float2*)&addend[off];
                        v0 += ad.x; v1 += ad.y;
                    }
                    float2 ov = (mode == 3)
                        ? make_float2(tf32r(v0), tf32r(v1))
                        : make_float2(v0, v1);
                    *(float2*)&C[off] = ov;
                } else if (mode == 1) {
                    if (r < cval) {
                        float g0 = 0.5f * v0 * (1.0f + erff(v0 * 0.70710678118f));
                        float g1 = 0.5f * v1 * (1.0f + erff(v1 * 0.70710678118f));
                        float2 ov = make_float2(tf32r(g0), tf32r(g1));
                        *(float2*)&C[(size_t)r * Nn + col] = ov;
                    }
                } else {
                    if (r < cval) {
                        int tok = rowidx[r];
                        float w = rowsw[r];
                        size_t off = (size_t)tok * Nn + col;
                        float2 old = *(const float2*)&C[off];
                        float2 ov = make_float2(old.x + v0 * w, old.y + v1 * w);
                        *(float2*)&C[off] = ov;
                    }
                }
            }
        }
    }
}

// ---------------- attention: TF32 mma flash, 128q x (b,h) per block ---------
// smem: Ks[64key][64d] + Vt[64d][64kk] + Ps[128q][64] (also Q/V staging),
// all XOR-chunk swizzled: float (r,k) at r*64 + ((k>>2)^(r&7))*4 + (k&3).
#define ATT_SMEM ((4096 + 4096 + 8192) * (int)sizeof(float))
__global__ __launch_bounds__(256) void attn_mma_kernel(
    const float* __restrict__ qkv, float* __restrict__ y)
{
    extern __shared__ float sm[];
    float* Ks = sm;
    float* Vt = sm + 4096;
    float* Ps = sm + 8192;

    int bh = blockIdx.x;
    int b = bh >> 4, h = bh & 15;
    int q0 = blockIdx.y * 128;
    int tid = threadIdx.x, lane = tid & 31, wid = tid >> 5;
    int g = lane >> 2, c = lane & 3;
    int qb = wid * 16;
    float slope = exp2f(-0.5f * (float)(h + 1));

    const float* qkvb = qkv + (size_t)(b * NN_SEQ) * (3 * DD);

    // stage Q tile (128x64) into Ps, swizzled
    for (int i = tid; i < 128 * 16; i += 256) {
        int r = i >> 4, ch = i & 15;
        float4 v = *(const float4*)&qkvb[(size_t)(q0 + r) * (3 * DD) + h * DH + ch * 4];
        *(float4*)&Ps[r * 64 + ((ch ^ (r & 7)) << 2)] = v;
    }
    __syncthreads();

    // Q fragments to registers, scaled by 1/8 (exact power of 2; tf32-clean)
    uint32_t qf[8][4];
#pragma unroll
    for (int s = 0; s < 8; s++) {
        const float* p0 = &Ps[(qb + g) * 64];
        const float* p1 = &Ps[(qb + 8 + g) * 64];
        int sw0 = (((2 * s) ^ g) << 2) + c;
        int sw1 = (((2 * s + 1) ^ g) << 2) + c;
        qf[s][0] = __float_as_uint(p0[sw0] * 0.125f);
        qf[s][1] = __float_as_uint(p1[sw0] * 0.125f);
        qf[s][2] = __float_as_uint(p0[sw1] * 0.125f);
        qf[s][3] = __float_as_uint(p1[sw1] * 0.125f);
    }

    float oa[8][4];
#pragma unroll
    for (int i = 0; i < 8; i++)
#pragma unroll
        for (int j = 0; j < 4; j++) oa[i][j] = 0.f;
    float m_lo = -1e30f, m_hi = -1e30f, l_lo = 0.f, l_hi = 0.f;
    int qlo = q0 + qb + g, qhi = qlo + 8;

    for (int kt = 0; kt < NN_SEQ; kt += 64) {
        __syncthreads();   // protect Ps/Ks/Vt reuse across iterations
        // load K -> Ks, V -> Ps staging (row-major, swizzled)
        for (int i = tid; i < 64 * 16; i += 256) {
            int r = i >> 4, ch = i & 15;
            size_t rowoff = (size_t)(kt + r) * (3 * DD) + h * DH + ch * 4;
            int dst = r * 64 + ((ch ^ (r & 7)) << 2);
            *(float4*)&Ks[dst] = *(const float4*)&qkvb[DD + rowoff];
            *(float4*)&Ps[dst] = *(const float4*)&qkvb[2 * DD + rowoff];
        }
        __syncthreads();

        // transpose V: Ps[kk][d] -> Vt[d][kk]
        {
            int d = tid & 63, kg = tid >> 6;
#pragma unroll
            for (int i = 0; i < 16; i++) {
                int kk = kg * 16 + i;
                float v = Ps[kk * 64 + (((d >> 2) ^ (kk & 7)) << 2) + (d & 3)];
                Vt[d * 64 + (((kk >> 2) ^ (d & 7)) << 2) + (kk & 3)] = v;
            }
        }

        // S = Q @ K^T
        float sa[8][4];
#pragma unroll
        for (int i = 0; i < 8; i++)
#pragma unroll
            for (int j = 0; j < 4; j++) sa[i][j] = 0.f;
#pragma unroll
        for (int s = 0; s < 8; s++) {
            int sw0 = (((2 * s) ^ g) << 2) + c;
            int sw1 = (((2 * s + 1) ^ g) << 2) + c;
#pragma unroll
            for (int nt = 0; nt < 8; nt++) {
                const float* pk = &Ks[(nt * 8 + g) * 64];
                uint32_t bf[2];
                bf[0] = __float_as_uint(pk[sw0]);
                bf[1] = __float_as_uint(pk[sw1]);
                mma_tf32(sa[nt], qf[s], bf);
            }
        }
        __syncthreads();   // Vt writes visible; staging reads complete

        // ALiBi + online softmax (rows qlo, qhi owned by lanes 4g..4g+3)
        float mx_lo = -1e30f, mx_hi = -1e30f;
#pragma unroll
        for (int nt = 0; nt < 8; nt++) {
            int k0 = kt + nt * 8 + 2 * c;
            float d0 = (k0 > qlo) ? (float)(k0 - qlo) : 0.f;
            float d1 = (k0 + 1 > qlo) ? (float)(k0 + 1 - qlo) : 0.f;
            float d2 = (k0 > qhi) ? (float)(k0 - qhi) : 0.f;
            float d3 = (k0 + 1 > qhi) ? (float)(k0 + 1 - qhi) : 0.f;
            sa[nt][0] -= slope * d0; sa[nt][1] -= slope * d1;
            sa[nt][2] -= slope * d2; sa[nt][3] -= slope * d3;
            mx_lo = fmaxf(mx_lo, fmaxf(sa[nt][0], sa[nt][1]));
            mx_hi = fmaxf(mx_hi, fmaxf(sa[nt][2], sa[nt][3]));
        }
        mx_lo = fmaxf(mx_lo, __shfl_xor_sync(0xffffffffu, mx_lo, 1));
        mx_lo = fmaxf(mx_lo, __shfl_xor_sync(0xffffffffu, mx_lo, 2));
        mx_hi = fmaxf(mx_hi, __shfl_xor_sync(0xffffffffu, mx_hi, 1));
        mx_hi = fmaxf(mx_hi, __shfl_xor_sync(0xffffffffu, mx_hi, 2));
        float mn_lo = fmaxf(m_lo, mx_lo), mn_hi = fmaxf(m_hi, mx_hi);
        float cc_lo = __expf(m_lo - mn_lo), cc_hi = __expf(m_hi - mn_hi);
        m_lo = mn_lo; m_hi = mn_hi;

        float rs_lo = 0.f, rs_hi = 0.f;
#pragma unroll
        for (int nt = 0; nt < 8; nt++) {
            float p0 = __expf(sa[nt][0] - mn_lo), p1 = __expf(sa[nt][1] - mn_lo);
            float p2 = __expf(sa[nt][2] - mn_hi), p3 = __expf(sa[nt][3] - mn_hi);
            rs_lo += p0 + p1; rs_hi += p2 + p3;
            int col = nt * 8 + 2 * c;
            int ch = col >> 2, off = col & 3;
            *(float2*)&Ps[(qb + g) * 64 + ((ch ^ g) << 2) + off] =
                make_float2(tf32r(p0), tf32r(p1));
            *(float2*)&Ps[(qb + 8 + g) * 64 + ((ch ^ g) << 2) + off] =
                make_float2(tf32r(p2), tf32r(p3));
        }
        rs_lo += __shfl_xor_sync(0xffffffffu, rs_lo, 1);
        rs_lo += __shfl_xor_sync(0xffffffffu, rs_lo, 2);
        rs_hi += __shfl_xor_sync(0xffffffffu, rs_hi, 1);
        rs_hi += __shfl_xor_sync(0xffffffffu, rs_hi, 2);
        l_lo = l_lo * cc_lo + rs_lo;
        l_hi = l_hi * cc_hi + rs_hi;
#pragma unroll
        for (int nt = 0; nt < 8; nt++) {
            oa[nt][0] *= cc_lo; oa[nt][1] *= cc_lo;
            oa[nt][2] *= cc_hi; oa[nt][3] *= cc_hi;
        }
        __syncwarp();

        // O += P @ V  (Ps rows are warp-private; Vt synced above)
#pragma unroll
        for (int s2 = 0; s2 < 8; s2++) {
            int sw0 = (((2 * s2) ^ g) << 2) + c;
            int sw1 = (((2 * s2 + 1) ^ g) << 2) + c;
            const float* pl = &Ps[(qb + g) * 64];
            const float* ph = &Ps[(qb + 8 + g) * 64];
            uint32_t af[4];
            af[0] = __float_as_uint(pl[sw0]);
            af[1] = __float_as_uint(ph[sw0]);
            af[2] = __float_as_uint(pl[sw1]);
            af[3] = __float_as_uint(ph[sw1]);
#pragma unroll
            for (int nt = 0; nt < 8; nt++) {
                const float* pv = &Vt[(nt * 8 + g) * 64];
                uint32_t bf[2];
                bf[0] = __float_as_uint(pv[sw0]);
                bf[1] = __float_as_uint(pv[sw1]);
                mma_tf32(oa[nt], af, bf);
            }
        }
    }

    float il_lo = 1.0f / l_lo, il_hi = 1.0f / l_hi;
#pragma unroll
    for (int nt = 0; nt < 8; nt++) {
        int col = h * DH + nt * 8 + 2 * c;
        size_t rlo = (size_t)(b * NN_SEQ + qlo) * DD + col;
        *(float2*)&y[rlo] =
            make_float2(tf32r(oa[nt][0] * il_lo), tf32r(oa[nt][1] * il_lo));
        *(float2*)&y[rlo + 8 * DD] =
            make_float2(tf32r(oa[nt][2] * il_hi), tf32r(oa[nt][3] * il_hi));
    }
}

// ---------------- router: gates + top-2 weights -----------------------------
__global__ __launch_bounds__(128) void router_kernel(
    const float* __restrict__ xf, const float* __restrict__ rw)
{
    int t = blockIdx.x;
    int lane = threadIdx.x & 31, wrp = threadIdx.x >> 5;
    const float* xr = xf + (size_t)t * DD;
    const float* wr = rw + (size_t)wrp * DD;
    float s = 0.f;
    for (int i = lane; i < DD; i += 32) s += xr[i] * wr[i];
#pragma unroll
    for (int o = 16; o > 0; o >>= 1) s += __shfl_xor_sync(0xffffffffu, s, o);
    __shared__ float sh[4];
    if (lane == 0) sh[wrp] = s;
    __syncthreads();
    if (threadIdx.x == 0) {
        float g[4]; float mx = -1e30f;
#pragma unroll
        for (int e = 0; e < EE; e++) { g[e] = sh[e]; mx = fmaxf(mx, g[e]); }
        float sum = 0.f;
#pragma unroll
        for (int e = 0; e < EE; e++) { g[e] = __expf(g[e] - mx); sum += g[e]; }
        float inv = 1.0f / sum;
#pragma unroll
        for (int e = 0; e < EE; e++) { g[e] *= inv; g_gates[t * EE + e] = g[e]; }
        int i1 = 0;
#pragma unroll
        for (int e = 1; e < EE; e++) if (g[e] > g[i1]) i1 = e;
        int i2 = -1;
#pragma unroll
        for (int e = 0; e < EE; e++)
            if (e != i1 && (i2 < 0 || g[e] > g[i2])) i2 = e;
        float norm = fmaxf(g[i1] + g[i2], 1e-9f);
        float w4[4] = {0.f, 0.f, 0.f, 0.f};
        w4[i1] = g[i1] / norm;
        w4[i2] = g[i2] / norm;
#pragma unroll
        for (int e = 0; e < EE; e++) g_wts[t * EE + e] = w4[e];
    }
}

// ---------------- expert token lists ----------------------------------------
__global__ void clear_cnt_kernel() {
    if (threadIdx.x < EE) g_cnt[threadIdx.x] = 0;
}

__global__ __launch_bounds__(256) void build_lists_kernel() {
    int t = blockIdx.x * 256 + threadIdx.x;
    if (t >= TT) return;
#pragma unroll
    for (int e = 0; e < EE; e++) {
        float w = g_wts[t * EE + e];
        if (w > 0.f) {
            int p = atomicAdd(&g_cnt[e], 1);
            g_list[e * TT + p] = t;
            g_lw[e * TT + p] = w;
        }
    }
}

// ---------------- deterministic aux reduction -------------------------------
__global__ __launch_bounds__(256) void aux_reduce_kernel()
{
    int tid = threadIdx.x;
    float sg[EE] = {0.f, 0.f, 0.f, 0.f};
    float sc[EE] = {0.f, 0.f, 0.f, 0.f};
    for (int t = tid; t < TT; t += 256) {
#pragma unroll
        for (int e = 0; e < EE; e++) {
            sg[e] += g_gates[t * EE + e];
            sc[e] += (g_wts[t * EE + e] > 0.f) ? 1.f : 0.f;
        }
    }
    __shared__ float sh[256];
    float aux = 0.f;
#pragma unroll
    for (int e = 0; e < EE; e++) {
        sh[tid] = sg[e]; __syncthreads();
        for (int o = 128; o > 0; o >>= 1) {
            if (tid < o) sh[tid] += sh[tid + o];
            __syncthreads();
        }
        float tot_g = sh[0]; __syncthreads();
        sh[tid] = sc[e]; __syncthreads();
        for (int o = 128; o > 0; o >>= 1) {
            if (tid < o) sh[tid] += sh[tid + o];
            __syncthreads();
        }
        float tot_c = sh[0]; __syncthreads();
        aux += (tot_g / (float)TT) * (tot_c / (float)TT);
    }
    if (tid == 0) g_auxval[0] = (float)EE * aux;
}

// ---------------- final: + trend depthwise conv(k=5) + aux ------------------
__global__ __launch_bounds__(256) void final_kernel(
    const float* __restrict__ tw, const float* __restrict__ tb,
    float* __restrict__ out, int write_aux)
{
    int bn = blockIdx.x;
    int b = bn / NN_SEQ, n = bn % NN_SEQ;
    int tid = threadIdx.x;
#pragma unroll
    for (int i = 0; i < 4; i++) {
        int d = tid + i * 256;
        float vsum = g_xs[(size_t)bn * DD + d] + tb[d];
#pragma unroll
        for (int j = 0; j < 5; j++) {
            int nn = n - 2 + j;
            if (nn >= 0 && nn < NN_SEQ)
                vsum += tw[d * 5 + j] * g_Tr[((size_t)b * NN_SEQ + nn) * DD + d];
        }
        out[(size_t)bn * DD + d] = vsum;
    }
    if (bn == 0 && tid == 0 && write_aux)
        out[(size_t)BB * NN_SEQ * DD] = g_auxval[0];
}

// ---------------- host orchestration ---------------------------------------
extern "C" void kernel_launch(void* const* d_in, const int* in_sizes, int n_in,
                              void* d_out, int out_size)
{
    const float* x    = (const float*)d_in[0];
    const float* qw   = (const float*)d_in[1];
    const float* qb   = (const float*)d_in[2];
    const float* kw   = (const float*)d_in[3];
    const float* kb   = (const float*)d_in[4];
    const float* vw   = (const float*)d_in[5];
    const float* vb   = (const float*)d_in[6];
    const float* ow   = (const float*)d_in[7];
    const float* ob   = (const float*)d_in[8];
    const float* n1g  = (const float*)d_in[9];
    const float* n1b  = (const float*)d_in[10];
    const float* n2g  = (const float*)d_in[11];
    const float* n2b  = (const float*)d_in[12];
    const float* alpha= (const float*)d_in[13];
    const float* dw7  = (const float*)d_in[14];
    const float* dw25 = (const float*)d_in[15];
    const float* dw49 = (const float*)d_in[16];
    const float* rw   = (const float*)d_in[17];
    const float* ew1  = (const float*)d_in[18];
    const float* eb1  = (const float*)d_in[19];
    const float* ew2  = (const float*)d_in[20];
    const float* eb2  = (const float*)d_in[21];
    const float* tw   = (const float*)d_in[22];
    const float* tb   = (const float*)d_in[23];
    float* out = (float*)d_out;

    float *p_Sn, *p_qkv, *p_y, *p_xs, *p_xf, *p_xfr, *p_h, *p_S, *p_lw, *p_wr;
    int *p_list, *p_cnt;
    cudaGetSymbolAddress((void**)&p_Sn, g_Sn);
    cudaGetSymbolAddress((void**)&p_qkv, g_qkv);
    cudaGetSymbolAddress((void**)&p_y,  g_y);
    cudaGetSymbolAddress((void**)&p_xs, g_xs);
    cudaGetSymbolAddress((void**)&p_xf, g_xf);
    cudaGetSymbolAddress((void**)&p_xfr, g_xfr);
    cudaGetSymbolAddress((void**)&p_h,  g_h);
    cudaGetSymbolAddress((void**)&p_S,  g_S);
    cudaGetSymbolAddress((void**)&p_lw,  g_lw);
    cudaGetSymbolAddress((void**)&p_list, g_list);
    cudaGetSymbolAddress((void**)&p_cnt,  g_cnt);
    cudaGetSymbolAddress((void**)&p_wr,  g_wr);
    float* p_qkvb;
    cudaGetSymbolAddress((void**)&p_qkvb, g_qkvb);

    cudaFuncSetAttribute(attn_mma_kernel,
                         cudaFuncAttributeMaxDynamicSharedMemorySize, ATT_SMEM);
    cudaFuncSetAttribute(gemm_tf32,
                         cudaFuncAttributeMaxDynamicSharedMemorySize, GSMEM);

    // 0) pre-round weights; concat QKV biases
    round_tf32_kernel<<<(DD * DD) / 4096, 256>>>(qw, p_wr + WR_Q, DD * DD);
    round_tf32_kernel<<<(DD * DD) / 4096, 256>>>(kw, p_wr + WR_K, DD * DD);
    round_tf32_kernel<<<(DD * DD) / 4096, 256>>>(vw, p_wr + WR_V, DD * DD);
    round_tf32_kernel<<<(DD * DD) / 4096, 256>>>(ow, p_wr + WR_O, DD * DD);
    round_tf32_kernel<<<(EE * MH * DD) / 4096, 256>>>(ew1, p_wr + WR_E1, EE * MH * DD);
    round_tf32_kernel<<<(EE * MH * DD) / 4096, 256>>>(ew2, p_wr + WR_E2, EE * MH * DD);
    concat_bias_kernel<<<(DD + 255) / 256, 256>>>(qb, kb, vb);

    // 1) decomposition + seasonal + LN1 (Sn rounded)
    decomp_ln1_kernel<<<BB * NN_SEQ, 256>>>(x, alpha, dw7, dw25, dw49, n1g, n1b);

    // 2) fused QKV projection -> g_qkv [T, 3072], rounded (mode 3)
    gemm_tf32<<<dim3(3 * DD / 128, TT / 128), 256, GSMEM>>>(
        p_Sn, p_wr + WR_Q, p_qkvb, nullptr, p_qkv, TT, 3 * DD, DD, 3,
        nullptr, nullptr, nullptr);

    // 3) ALiBi attention: TF32 mma flash tiles
    attn_mma_kernel<<<dim3(BB * HH, NN_SEQ / 128), 256, ATT_SMEM>>>(p_qkv, p_y);

    // 4) output projection fused with residual: x_s = S + (y @ ow^T + ob)
    dim3 gQ(DD / 128, TT / 128);
    gemm_tf32<<<gQ, 256, GSMEM>>>(p_y, p_wr + WR_O, ob, p_S, p_xs, TT, DD, DD, 0,
                                  nullptr, nullptr, nullptr);

    // 5) LN2 -> xf (exact) + xfr (rounded)
    ln_kernel<<<BB * NN_SEQ, 256>>>(p_xs, n2g, n2b, p_xf, p_xfr);

    // 6) router, token lists, aux
    router_kernel<<<TT, 128>>>(p_xf, rw);
    clear_cnt_kernel<<<1, 32>>>();
    build_lists_kernel<<<TT / 256, 256>>>();
    aux_reduce_kernel<<<1, 256>>>();

    // 7) sparse MoE: gather -> GEMM1(gelu, rounded h) -> GEMM2(scatter +=)
    dim3 gE1(MH / 128, TT / 128);
    dim3 gE2(DD / 128, TT / 128);
    for (int e = 0; e < EE; e++) {
        gemm_tf32<<<gE1, 256, GSMEM>>>(p_xfr, p_wr + WR_E1 + (size_t)e * MH * DD,
                                       eb1 + (size_t)e * MH,
                                       nullptr, p_h, TT, MH, DD, 1,
                                       p_list + e * TT, p_cnt + e, nullptr);
        gemm_tf32<<<gE2, 256, GSMEM>>>(p_h, p_wr + WR_E2 + (size_t)e * DD * MH,
                                       eb2 + (size_t)e * DD,
                                       nullptr, p_xs, TT, DD, MH, 2,
                                       p_list + e * TT, p_cnt + e, p_lw + e * TT);
    }

    // 8) trend conv + final sum + aux scalar
    int write_aux = (out_size > BB * NN_SEQ * DD) ? 1 : 0;
    final_kernel<<<BB * NN_SEQ, 256>>>(tw, tb, out, write_aux);
}

// round 12
// speedup vs baseline: 1.2193x; 1.2193x over previous
#include <cuda_runtime.h>
#include <math.h>
#include <stdint.h>

#define BB 8
#define NN_SEQ 1024
#define DD 1024
#define HH 16
#define DH 64
#define TT (BB * NN_SEQ)      // 8192 tokens
#define EE 4
#define MH 2048
#define LN_EPS 1e-5f

// ---------------- scratch (device globals; no allocations allowed) ----------
__device__ float g_Tr[BB * NN_SEQ * DD];
__device__ float g_S [BB * NN_SEQ * DD];
__device__ float g_Sn[BB * NN_SEQ * DD];    // tf32-rounded at write
__device__ float g_qkv[TT * 3 * DD];        // fused QKV, tf32-rounded at write
__device__ float g_y [BB * NN_SEQ * DD];    // tf32-rounded at write
__device__ float g_xs[BB * NN_SEQ * DD];
__device__ float g_xf[BB * NN_SEQ * DD];    // exact (router input)
__device__ float g_xfr[BB * NN_SEQ * DD];   // tf32-rounded copy (GEMM input)
__device__ float g_h [TT * MH];             // tf32-rounded at write
__device__ float g_gates[TT * EE];
__device__ float g_wts  [TT * EE];
__device__ int   g_list [EE * TT];
__device__ float g_lw   [EE * TT];
__device__ int   g_cnt  [EE];
__device__ float g_auxval[1];
__device__ float g_qkvb[3 * DD];
// pre-rounded weights: qw,kw,vw,ow (4 x 1M), ew1 (4 x 2M), ew2 (4 x 2M)
#define WR_Q  0
#define WR_K  (DD * DD)
#define WR_V  (2 * DD * DD)
#define WR_O  (3 * DD * DD)
#define WR_E1 (4 * DD * DD)
#define WR_E2 (4 * DD * DD + EE * MH * DD)
#define WR_TOTAL (4 * DD * DD + 2 * EE * MH * DD)
__device__ float g_wr[WR_TOTAL];

// ---------------- tf32 rounding helpers -------------------------------------
__device__ __forceinline__ uint32_t f2tf(float f) {
    uint32_t u;
    asm("cvt.rna.tf32.f32 %0, %1;" : "=r"(u) : "f"(f));
    return u;
}
__device__ __forceinline__ float tf32r(float f) {
    return __uint_as_float(f2tf(f));
}

__global__ __launch_bounds__(256) void round_tf32_kernel(
    const float* __restrict__ src, float* __restrict__ dst, int n)
{
    int base = (blockIdx.x * 256 + threadIdx.x) * 16;
#pragma unroll
    for (int j = 0; j < 4; j++) {
        int i = base + j * 4;
        if (i < n) {
            float4 v = *(const float4*)&src[i];
            v.x = tf32r(v.x); v.y = tf32r(v.y);
            v.z = tf32r(v.z); v.w = tf32r(v.w);
            *(float4*)&dst[i] = v;
        }
    }
}

__global__ __launch_bounds__(256) void concat_bias_kernel(
    const float* __restrict__ qb, const float* __restrict__ kb,
    const float* __restrict__ vb)
{
    int i = blockIdx.x * 256 + threadIdx.x;
    if (i < DD) {
        g_qkvb[i] = qb[i];
        g_qkvb[DD + i] = kb[i];
        g_qkvb[2 * DD + i] = vb[i];
    }
}

// ---------------- decomposition: smem-tiled depthwise convs -----------------
// block = (d-chunk 32, n-chunk 128, b); smem window 176 x 32 loaded ONCE.
#define DNT 128
#define DHALO 24
#define DROWS (DNT + 2 * DHALO)   // 176
__global__ __launch_bounds__(256) void decomp_kernel(
    const float* __restrict__ x, const float* __restrict__ alpha,
    const float* __restrict__ dw7, const float* __restrict__ dw25,
    const float* __restrict__ dw49)
{
    __shared__ float xs[DROWS][32];
    int d0 = blockIdx.x * 32;
    int n0 = blockIdx.y * DNT;
    int b  = blockIdx.z;
    int tid = threadIdx.x;
    int d = tid & 31, nr = tid >> 5;   // lane d = bank d: conflict-free

    float a0 = alpha[0], a1 = alpha[1], a2 = alpha[2];
    float mx = fmaxf(a0, fmaxf(a1, a2));
    float e0 = __expf(a0 - mx), e1 = __expf(a1 - mx), e2 = __expf(a2 - mx);
    float inv = 1.0f / (e0 + e1 + e2);
    float w0 = e0 * inv, w1 = e1 * inv, w2 = e2 * inv;

    const float* xb = x + (size_t)b * NN_SEQ * DD + d0 + d;
    for (int i = nr; i < DROWS; i += 8) {
        int idx = n0 - DHALO + i;
        idx = idx < 0 ? -idx : idx;
        idx = idx >= NN_SEQ ? (2 * NN_SEQ - 2 - idx) : idx;
        xs[i][d] = xb[(size_t)idx * DD];
    }

    // conv weights for this channel -> registers (reused 16x)
    int dg = d0 + d;
    float w7r[7], w25r[25], w49r[49];
#pragma unroll
    for (int j = 0; j < 7; j++)  w7r[j]  = dw7 [dg * 7  + j];
#pragma unroll
    for (int j = 0; j < 25; j++) w25r[j] = dw25[dg * 25 + j];
#pragma unroll
    for (int j = 0; j < 49; j++) w49r[j] = dw49[dg * 49 + j];
    __syncthreads();

    for (int jo = 0; jo < 16; jo++) {
        int nl = nr + 8 * jo;            // 0..127
        float t7 = 0.f, t25 = 0.f, t49 = 0.f;
#pragma unroll
        for (int j = 0; j < 7; j++)  t7  += w7r[j]  * xs[nl + 21 + j][d];
#pragma unroll
        for (int j = 0; j < 25; j++) t25 += w25r[j] * xs[nl + 12 + j][d];
#pragma unroll
        for (int j = 0; j < 49; j++) t49 += w49r[j] * xs[nl + j][d];
        float tr = w0 * t7 + w1 * t25 + w2 * t49;
        float sv = xs[nl + 24][d] - tr;
        size_t off = ((size_t)(b * NN_SEQ + n0 + nl)) * DD + dg;
        g_Tr[off] = tr;
        g_S [off] = sv;
    }
}

// ---------------- generic LN kernel (nullable outputs) ----------------------
__global__ __launch_bounds__(256) void ln_kernel(
    const float* __restrict__ in, const float* __restrict__ g,
    const float* __restrict__ bta, float* __restrict__ out,
    float* __restrict__ out_r)
{
    int bn = blockIdx.x;
    int tid = threadIdx.x;
    const float* row = in + (size_t)bn * DD;
    float v[4]; float sum = 0.f, sumsq = 0.f;
#pragma unroll
    for (int i = 0; i < 4; i++) {
        v[i] = row[tid + i * 256];
        sum += v[i]; sumsq += v[i] * v[i];
    }
    __shared__ float sh1[256], sh2[256];
    sh1[tid] = sum; sh2[tid] = sumsq;
    __syncthreads();
    for (int o = 128; o > 0; o >>= 1) {
        if (tid < o) { sh1[tid] += sh1[tid + o]; sh2[tid] += sh2[tid + o]; }
        __syncthreads();
    }
    float mean = sh1[0] * (1.0f / DD);
    float var  = sh2[0] * (1.0f / DD) - mean * mean;
    float rstd = rsqrtf(var + LN_EPS);
#pragma unroll
    for (int i = 0; i < 4; i++) {
        int d = tid + i * 256;
        float ov = (v[i] - mean) * rstd * g[d] + bta[d];
        if (out)   out[(size_t)bn * DD + d] = ov;
        if (out_r) out_r[(size_t)bn * DD + d] = tf32r(ov);
    }
}

// ---------------- TF32 tensor-core NT GEMM, cp.async 3-stage pipeline -------
// All operands MUST be pre-rounded to tf32.
// mode 0: C = acc + bias (+ addend)            (dense, exact f32 out)
// mode 3: C = tf32r(acc + bias)                (dense, rounded out)
// mode 1: C[row] = tf32r(gelu(acc+bias)), A rows gathered via rowidx, row<cnt
// mode 2: C[rowidx[row]] += (acc + bias) * rowsw[row], row<cnt (scatter)
__device__ __forceinline__ void mma_tf32(float* d, const uint32_t* a, const uint32_t* b) {
    asm volatile(
        "mma.sync.aligned.m16n8k8.row.col.f32.tf32.tf32.f32 "
        "{%0,%1,%2,%3}, {%4,%5,%6,%7}, {%8,%9}, {%0,%1,%2,%3};"
        : "+f"(d[0]), "+f"(d[1]), "+f"(d[2]), "+f"(d[3])
        : "r"(a[0]), "r"(a[1]), "r"(a[2]), "r"(a[3]),
          "r"(b[0]), "r"(b[1]));
}

__device__ __forceinline__ void cpa16(float* dst, const float* src) {
    uint32_t d = (uint32_t)__cvta_generic_to_shared(dst);
    asm volatile("cp.async.cg.shared.global [%0], [%1], 16;\n" :: "r"(d), "l"(src));
}

#define GSTG 3
#define GSMEM (GSTG * 4096 * 2 * (int)sizeof(float))   // 96 KB
__global__ __launch_bounds__(256, 2) void gemm_tf32(
    const float* __restrict__ A, const float* __restrict__ W,
    const float* __restrict__ bias, const float* __restrict__ addend,
    float* __restrict__ C, int M, int Nn, int K, int mode,
    const int* __restrict__ rowidx, const int* __restrict__ cnt_ptr,
    const float* __restrict__ rowsw)
{
    int m0 = blockIdx.y * 128, n0 = blockIdx.x * 128;
    int cval = cnt_ptr ? *cnt_ptr : M;
    if (m0 >= cval) return;

    extern __shared__ float sm[];
    float* Abuf = sm;                    // [GSTG][4096]
    float* Wbuf = sm + GSTG * 4096;      // [GSTG][4096]

    int tid = threadIdx.x;
    int lrow = tid >> 1;
    int cbase = (tid & 1) * 4;

    int arow = m0 + lrow;
    if (mode == 1 && rowidx) arow = rowidx[arow < cval ? arow : (cval - 1)];
    const float* Aptr = A + (size_t)arow * K + cbase * 4;
    const float* Wptr = W + (size_t)(n0 + lrow) * K + cbase * 4;

    int dsts[4];
#pragma unroll
    for (int j = 0; j < 4; j++)
        dsts[j] = lrow * 32 + ((cbase + j) ^ (lrow & 7)) * 4;

    int lane = tid & 31, wid = tid >> 5;
    int wm = wid >> 2, wn = wid & 3;
    int g = lane >> 2, c = lane & 3;

    float acc[4][4][4];
#pragma unroll
    for (int i = 0; i < 4; i++)
#pragma unroll
        for (int j = 0; j < 4; j++)
#pragma unroll
            for (int r = 0; r < 4; r++) acc[i][j][r] = 0.f;

    int nk = K / 32;
    // prologue: stages 0 and 1
#pragma unroll
    for (int st = 0; st < 2; st++) {
        if (st < nk) {
            int k0 = st * 32;
#pragma unroll
            for (int j = 0; j < 4; j++) {
                cpa16(Abuf + st * 4096 + dsts[j], Aptr + k0 + j * 4);
                cpa16(Wbuf + st * 4096 + dsts[j], Wptr + k0 + j * 4);
            }
            asm volatile("cp.async.commit_group;\n" ::);
        }
    }

    for (int it = 0; it < nk; it++) {
        if (it < nk - 1)
            asm volatile("cp.async.wait_group 1;\n" ::);
        else
            asm volatile("cp.async.wait_group 0;\n" ::);
        __syncthreads();

        int pf = it + 2;
        if (pf < nk) {
            int st = pf % GSTG;
            int k0 = pf * 32;
#pragma unroll
            for (int j = 0; j < 4; j++) {
                cpa16(Abuf + st * 4096 + dsts[j], Aptr + k0 + j * 4);
                cpa16(Wbuf + st * 4096 + dsts[j], Wptr + k0 + j * 4);
            }
            asm volatile("cp.async.commit_group;\n" ::);
        }

        const float* Ab = Abuf + (it % GSTG) * 4096;
        const float* Wb = Wbuf + (it % GSTG) * 4096;
#pragma unroll
        for (int s = 0; s < 4; s++) {
            int sw0 = ((2 * s) ^ g) * 4 + c;
            int sw1 = ((2 * s + 1) ^ g) * 4 + c;
            uint32_t af[4][4], bf[4][2];
#pragma unroll
            for (int mf = 0; mf < 4; mf++) {
                const float* pa = Ab + (wm * 64 + mf * 16 + g) * 32;
                af[mf][0] = __float_as_uint(pa[sw0]);
                af[mf][1] = __float_as_uint(pa[8 * 32 + sw0]);
                af[mf][2] = __float_as_uint(pa[sw1]);
                af[mf][3] = __float_as_uint(pa[8 * 32 + sw1]);
            }
#pragma unroll
            for (int nf = 0; nf < 4; nf++) {
                const float* pw = Wb + (wn * 32 + nf * 8 + g) * 32;
                bf[nf][0] = __float_as_uint(pw[sw0]);
                bf[nf][1] = __float_as_uint(pw[sw1]);
            }
#pragma unroll
            for (int mf = 0; mf < 4; mf++)
#pragma unroll
                for (int nf = 0; nf < 4; nf++)
                    mma_tf32(acc[mf][nf], af[mf], bf[nf]);
        }
    }

#pragma unroll
    for (int mf = 0; mf < 4; mf++) {
#pragma unroll
        for (int half = 0; half < 2; half++) {
            int r = m0 + wm * 64 + mf * 16 + g + half * 8;
#pragma unroll
            for (int nf = 0; nf < 4; nf++) {
                int col = n0 + wn * 32 + nf * 8 + 2 * c;
                float v0 = acc[mf][nf][half * 2 + 0];
                float v1 = acc[mf][nf][half * 2 + 1];
                if (bias) { v0 += bias[col]; v1 += bias[col + 1]; }
                if (mode == 0 || mode == 3) {
                    size_t off = (size_t)r * Nn + col;
                    if (addend) {
                        float2 ad = *(const float2*)&addend[off];
                        v0 += ad.x; v1 += ad.y;
                    }
                    float2 ov = (mode == 3)
                        ? make_float2(tf32r(v0), tf32r(v1))
                        : make_float2(v0, v1);
                    *(float2*)&C[off] = ov;
                } else if (mode == 1) {
                    if (r < cval) {
                        float g0 = 0.5f * v0 * (1.0f + erff(v0 * 0.70710678118f));
                        float g1 = 0.5f * v1 * (1.0f + erff(v1 * 0.70710678118f));
                        float2 ov = make_float2(tf32r(g0), tf32r(g1));
                        *(float2*)&C[(size_t)r * Nn + col] = ov;
                    }
                } else {
                    if (r < cval) {
                        int tok = rowidx[r];
                        float w = rowsw[r];
                        size_t off = (size_t)tok * Nn + col;
                        float2 old = *(const float2*)&C[off];
                        float2 ov = make_float2(old.x + v0 * w, old.y + v1 * w);
                        *(float2*)&C[off] = ov;
                    }
                }
            }
        }
    }
}

// ---------------- attention: TF32 mma flash, 128q x (b,h) per block ---------
#define ATT_SMEM ((4096 + 4096 + 8192) * (int)sizeof(float))
__global__ __launch_bounds__(256) void attn_mma_kernel(
    const float* __restrict__ qkv, float* __restrict__ y)
{
    extern __shared__ float sm[];
    float* Ks = sm;
    float* Vt = sm + 4096;
    float* Ps = sm + 8192;

    int bh = blockIdx.x;
    int b = bh >> 4, h = bh & 15;
    int q0 = blockIdx.y * 128;
    int tid = threadIdx.x, lane = tid & 31, wid = tid >> 5;
    int g = lane >> 2, c = lane & 3;
    int qb = wid * 16;
    float slope = exp2f(-0.5f * (float)(h + 1));

    const float* qkvb = qkv + (size_t)(b * NN_SEQ) * (3 * DD);

    // stage Q tile (128x64) into Ps, swizzled
    for (int i = tid; i < 128 * 16; i += 256) {
        int r = i >> 4, ch = i & 15;
        float4 v = *(const float4*)&qkvb[(size_t)(q0 + r) * (3 * DD) + h * DH + ch * 4];
        *(float4*)&Ps[r * 64 + ((ch ^ (r & 7)) << 2)] = v;
    }
    __syncthreads();

    uint32_t qf[8][4];
#pragma unroll
    for (int s = 0; s < 8; s++) {
        const float* p0 = &Ps[(qb + g) * 64];
        const float* p1 = &Ps[(qb + 8 + g) * 64];
        int sw0 = (((2 * s) ^ g) << 2) + c;
        int sw1 = (((2 * s + 1) ^ g) << 2) + c;
        qf[s][0] = __float_as_uint(p0[sw0] * 0.125f);
        qf[s][1] = __float_as_uint(p1[sw0] * 0.125f);
        qf[s][2] = __float_as_uint(p0[sw1] * 0.125f);
        qf[s][3] = __float_as_uint(p1[sw1] * 0.125f);
    }

    float oa[8][4];
#pragma unroll
    for (int i = 0; i < 8; i++)
#pragma unroll
        for (int j = 0; j < 4; j++) oa[i][j] = 0.f;
    float m_lo = -1e30f, m_hi = -1e30f, l_lo = 0.f, l_hi = 0.f;
    int qlo = q0 + qb + g, qhi = qlo + 8;

    for (int kt = 0; kt < NN_SEQ; kt += 64) {
        __syncthreads();
        for (int i = tid; i < 64 * 16; i += 256) {
            int r = i >> 4, ch = i & 15;
            size_t rowoff = (size_t)(kt + r) * (3 * DD) + h * DH + ch * 4;
            int dst = r * 64 + ((ch ^ (r & 7)) << 2);
            *(float4*)&Ks[dst] = *(const float4*)&qkvb[DD + rowoff];
            *(float4*)&Ps[dst] = *(const float4*)&qkvb[2 * DD + rowoff];
        }
        __syncthreads();

        // transpose V: Ps[kk][d] -> Vt[d][kk]
        {
            int d = tid & 63, kg = tid >> 6;
#pragma unroll
            for (int i = 0; i < 16; i++) {
                int kk = kg * 16 + i;
                float v = Ps[kk * 64 + (((d >> 2) ^ (kk & 7)) << 2) + (d & 3)];
                Vt[d * 64 + (((kk >> 2) ^ (d & 7)) << 2) + (kk & 3)] = v;
            }
        }

        // S = Q @ K^T
        float sa[8][4];
#pragma unroll
        for (int i = 0; i < 8; i++)
#pragma unroll
            for (int j = 0; j < 4; j++) sa[i][j] = 0.f;
#pragma unroll
        for (int s = 0; s < 8; s++) {
            int sw0 = (((2 * s) ^ g) << 2) + c;
            int sw1 = (((2 * s + 1) ^ g) << 2) + c;
#pragma unroll
            for (int nt = 0; nt < 8; nt++) {
                const float* pk = &Ks[(nt * 8 + g) * 64];
                uint32_t bf[2];
                bf[0] = __float_as_uint(pk[sw0]);
                bf[1] = __float_as_uint(pk[sw1]);
                mma_tf32(sa[nt], qf[s], bf);
            }
        }
        __syncthreads();

        float mx_lo = -1e30f, mx_hi = -1e30f;
#pragma unroll
        for (int nt = 0; nt < 8; nt++) {
            int k0 = kt + nt * 8 + 2 * c;
            float d0 = (k0 > qlo) ? (float)(k0 - qlo) : 0.f;
            float d1 = (k0 + 1 > qlo) ? (float)(k0 + 1 - qlo) : 0.f;
            float d2 = (k0 > qhi) ? (float)(k0 - qhi) : 0.f;
            float d3 = (k0 + 1 > qhi) ? (float)(k0 + 1 - qhi) : 0.f;
            sa[nt][0] -= slope * d0; sa[nt][1] -= slope * d1;
            sa[nt][2] -= slope * d2; sa[nt][3] -= slope * d3;
            mx_lo = fmaxf(mx_lo, fmaxf(sa[nt][0], sa[nt][1]));
            mx_hi = fmaxf(mx_hi, fmaxf(sa[nt][2], sa[nt][3]));
        }
        mx_lo = fmaxf(mx_lo, __shfl_xor_sync(0xffffffffu, mx_lo, 1));
        mx_lo = fmaxf(mx_lo, __shfl_xor_sync(0xffffffffu, mx_lo, 2));
        mx_hi = fmaxf(mx_hi, __shfl_xor_sync(0xffffffffu, mx_hi, 1));
        mx_hi = fmaxf(mx_hi, __shfl_xor_sync(0xffffffffu, mx_hi, 2));
        float mn_lo = fmaxf(m_lo, mx_lo), mn_hi = fmaxf(m_hi, mx_hi);
        float cc_lo = __expf(m_lo - mn_lo), cc_hi = __expf(m_hi - mn_hi);
        m_lo = mn_lo; m_hi = mn_hi;

        float rs_lo = 0.f, rs_hi = 0.f;
#pragma unroll
        for (int nt = 0; nt < 8; nt++) {
            float p0 = __expf(sa[nt][0] - mn_lo), p1 = __expf(sa[nt][1] - mn_lo);
            float p2 = __expf(sa[nt][2] - mn_hi), p3 = __expf(sa[nt][3] - mn_hi);
            rs_lo += p0 + p1; rs_hi += p2 + p3;
            int col = nt * 8 + 2 * c;
            int ch = col >> 2, off = col & 3;
            *(float2*)&Ps[(qb + g) * 64 + ((ch ^ g) << 2) + off] =
                make_float2(tf32r(p0), tf32r(p1));
            *(float2*)&Ps[(qb + 8 + g) * 64 + ((ch ^ g) << 2) + off] =
                make_float2(tf32r(p2), tf32r(p3));
        }
        rs_lo += __shfl_xor_sync(0xffffffffu, rs_lo, 1);
        rs_lo += __shfl_xor_sync(0xffffffffu, rs_lo, 2);
        rs_hi += __shfl_xor_sync(0xffffffffu, rs_hi, 1);
        rs_hi += __shfl_xor_sync(0xffffffffu, rs_hi, 2);
        l_lo = l_lo * cc_lo + rs_lo;
        l_hi = l_hi * cc_hi + rs_hi;
#pragma unroll
        for (int nt = 0; nt < 8; nt++) {
            oa[nt][0] *= cc_lo; oa[nt][1] *= cc_lo;
            oa[nt][2] *= cc_hi; oa[nt][3] *= cc_hi;
        }
        __syncwarp();

        // O += P @ V
#pragma unroll
        for (int s2 = 0; s2 < 8; s2++) {
            int sw0 = (((2 * s2) ^ g) << 2) + c;
            int sw1 = (((2 * s2 + 1) ^ g) << 2) + c;
            const float* pl = &Ps[(qb + g) * 64];
            const float* ph = &Ps[(qb + 8 + g) * 64];
            uint32_t af[4];
            af[0] = __float_as_uint(pl[sw0]);
            af[1] = __float_as_uint(ph[sw0]);
            af[2] = __float_as_uint(pl[sw1]);
            af[3] = __float_as_uint(ph[sw1]);
#pragma unroll
            for (int nt = 0; nt < 8; nt++) {
                const float* pv = &Vt[(nt * 8 + g) * 64];
                uint32_t bf[2];
                bf[0] = __float_as_uint(pv[sw0]);
                bf[1] = __float_as_uint(pv[sw1]);
                mma_tf32(oa[nt], af, bf);
            }
        }
    }

    float il_lo = 1.0f / l_lo, il_hi = 1.0f / l_hi;
#pragma unroll
    for (int nt = 0; nt < 8; nt++) {
        int col = h * DH + nt * 8 + 2 * c;
        size_t rlo = (size_t)(b * NN_SEQ + qlo) * DD + col;
        *(float2*)&y[rlo] =
            make_float2(tf32r(oa[nt][0] * il_lo), tf32r(oa[nt][1] * il_lo));
        *(float2*)&y[rlo + 8 * DD] =
            make_float2(tf32r(oa[nt][2] * il_hi), tf32r(oa[nt][3] * il_hi));
    }
}

// ---------------- router: gates + top-2 weights -----------------------------
__global__ __launch_bounds__(128) void router_kernel(
    const float* __restrict__ xf, const float* __restrict__ rw)
{
    int t = blockIdx.x;
    int lane = threadIdx.x & 31, wrp = threadIdx.x >> 5;
    const float* xr = xf + (size_t)t * DD;
    const float* wr = rw + (size_t)wrp * DD;
    float s = 0.f;
    for (int i = lane; i < DD; i += 32) s += xr[i] * wr[i];
#pragma unroll
    for (int o = 16; o > 0; o >>= 1) s += __shfl_xor_sync(0xffffffffu, s, o);
    __shared__ float sh[4];
    if (lane == 0) sh[wrp] = s;
    __syncthreads();
    if (threadIdx.x == 0) {
        float g[4]; float mx = -1e30f;
#pragma unroll
        for (int e = 0; e < EE; e++) { g[e] = sh[e]; mx = fmaxf(mx, g[e]); }
        float sum = 0.f;
#pragma unroll
        for (int e = 0; e < EE; e++) { g[e] = __expf(g[e] - mx); sum += g[e]; }
        float inv = 1.0f / sum;
#pragma unroll
        for (int e = 0; e < EE; e++) { g[e] *= inv; g_gates[t * EE + e] = g[e]; }
        int i1 = 0;
#pragma unroll
        for (int e = 1; e < EE; e++) if (g[e] > g[i1]) i1 = e;
        int i2 = -1;
#pragma unroll
        for (int e = 0; e < EE; e++)
            if (e != i1 && (i2 < 0 || g[e] > g[i2])) i2 = e;
        float norm = fmaxf(g[i1] + g[i2], 1e-9f);
        float w4[4] = {0.f, 0.f, 0.f, 0.f};
        w4[i1] = g[i1] / norm;
        w4[i2] = g[i2] / norm;
#pragma unroll
        for (int e = 0; e < EE; e++) g_wts[t * EE + e] = w4[e];
    }
}

// ---------------- expert token lists ----------------------------------------
__global__ void clear_cnt_kernel() {
    if (threadIdx.x < EE) g_cnt[threadIdx.x] = 0;
}

__global__ __launch_bounds__(256) void build_lists_kernel() {
    int t = blockIdx.x * 256 + threadIdx.x;
    if (t >= TT) return;
#pragma unroll
    for (int e = 0; e < EE; e++) {
        float w = g_wts[t * EE + e];
        if (w > 0.f) {
            int p = atomicAdd(&g_cnt[e], 1);
            g_list[e * TT + p] = t;
            g_lw[e * TT + p] = w;
        }
    }
}

// ---------------- deterministic aux reduction -------------------------------
__global__ __launch_bounds__(256) void aux_reduce_kernel()
{
    int tid = threadIdx.x;
    float sg[EE] = {0.f, 0.f, 0.f, 0.f};
    float sc[EE] = {0.f, 0.f, 0.f, 0.f};
    for (int t = tid; t < TT; t += 256) {
#pragma unroll
        for (int e = 0; e < EE; e++) {
            sg[e] += g_gates[t * EE + e];
            sc[e] += (g_wts[t * EE + e] > 0.f) ? 1.f : 0.f;
        }
    }
    __shared__ float sh[256];
    float aux = 0.f;
#pragma unroll
    for (int e = 0; e < EE; e++) {
        sh[tid] = sg[e]; __syncthreads();
        for (int o = 128; o > 0; o >>= 1) {
            if (tid < o) sh[tid] += sh[tid + o];
            __syncthreads();
        }
        float tot_g = sh[0]; __syncthreads();
        sh[tid] = sc[e]; __syncthreads();
        for (int o = 128; o > 0; o >>= 1) {
            if (tid < o) sh[tid] += sh[tid + o];
            __syncthreads();
        }
        float tot_c = sh[0]; __syncthreads();
        aux += (tot_g / (float)TT) * (tot_c / (float)TT);
    }
    if (tid == 0) g_auxval[0] = (float)EE * aux;
}

// ---------------- final: + trend depthwise conv(k=5) + aux ------------------
__global__ __launch_bounds__(256) void final_kernel(
    const float* __restrict__ tw, const float* __restrict__ tb,
    float* __restrict__ out, int write_aux)
{
    int bn = blockIdx.x;
    int b = bn / NN_SEQ, n = bn % NN_SEQ;
    int tid = threadIdx.x;
#pragma unroll
    for (int i = 0; i < 4; i++) {
        int d = tid + i * 256;
        float vsum = g_xs[(size_t)bn * DD + d] + tb[d];
#pragma unroll
        for (int j = 0; j < 5; j++) {
            int nn = n - 2 + j;
            if (nn >= 0 && nn < NN_SEQ)
                vsum += tw[d * 5 + j] * g_Tr[((size_t)b * NN_SEQ + nn) * DD + d];
        }
        out[(size_t)bn * DD + d] = vsum;
    }
    if (bn == 0 && tid == 0 && write_aux)
        out[(size_t)BB * NN_SEQ * DD] = g_auxval[0];
}

// ---------------- host orchestration ---------------------------------------
extern "C" void kernel_launch(void* const* d_in, const int* in_sizes, int n_in,
                              void* d_out, int out_size)
{
    const float* x    = (const float*)d_in[0];
    const float* qw   = (const float*)d_in[1];
    const float* qb   = (const float*)d_in[2];
    const float* kw   = (const float*)d_in[3];
    const float* kb   = (const float*)d_in[4];
    const float* vw   = (const float*)d_in[5];
    const float* vb   = (const float*)d_in[6];
    const float* ow   = (const float*)d_in[7];
    const float* ob   = (const float*)d_in[8];
    const float* n1g  = (const float*)d_in[9];
    const float* n1b  = (const float*)d_in[10];
    const float* n2g  = (const float*)d_in[11];
    const float* n2b  = (const float*)d_in[12];
    const float* alpha= (const float*)d_in[13];
    const float* dw7  = (const float*)d_in[14];
    const float* dw25 = (const float*)d_in[15];
    const float* dw49 = (const float*)d_in[16];
    const float* rw   = (const float*)d_in[17];
    const float* ew1  = (const float*)d_in[18];
    const float* eb1  = (const float*)d_in[19];
    const float* ew2  = (const float*)d_in[20];
    const float* eb2  = (const float*)d_in[21];
    const float* tw   = (const float*)d_in[22];
    const float* tb   = (const float*)d_in[23];
    float* out = (float*)d_out;

    float *p_Sn, *p_qkv, *p_y, *p_xs, *p_xf, *p_xfr, *p_h, *p_S, *p_lw, *p_wr;
    int *p_list, *p_cnt;
    cudaGetSymbolAddress((void**)&p_Sn, g_Sn);
    cudaGetSymbolAddress((void**)&p_qkv, g_qkv);
    cudaGetSymbolAddress((void**)&p_y,  g_y);
    cudaGetSymbolAddress((void**)&p_xs, g_xs);
    cudaGetSymbolAddress((void**)&p_xf, g_xf);
    cudaGetSymbolAddress((void**)&p_xfr, g_xfr);
    cudaGetSymbolAddress((void**)&p_h,  g_h);
    cudaGetSymbolAddress((void**)&p_S,  g_S);
    cudaGetSymbolAddress((void**)&p_lw,  g_lw);
    cudaGetSymbolAddress((void**)&p_list, g_list);
    cudaGetSymbolAddress((void**)&p_cnt,  g_cnt);
    cudaGetSymbolAddress((void**)&p_wr,  g_wr);
    float* p_qkvb;
    cudaGetSymbolAddress((void**)&p_qkvb, g_qkvb);

    cudaFuncSetAttribute(attn_mma_kernel,
                         cudaFuncAttributeMaxDynamicSharedMemorySize, ATT_SMEM);
    cudaFuncSetAttribute(gemm_tf32,
                         cudaFuncAttributeMaxDynamicSharedMemorySize, GSMEM);

    // 0) pre-round weights; concat QKV biases
    round_tf32_kernel<<<(DD * DD) / 4096, 256>>>(qw, p_wr + WR_Q, DD * DD);
    round_tf32_kernel<<<(DD * DD) / 4096, 256>>>(kw, p_wr + WR_K, DD * DD);
    round_tf32_kernel<<<(DD * DD) / 4096, 256>>>(vw, p_wr + WR_V, DD * DD);
    round_tf32_kernel<<<(DD * DD) / 4096, 256>>>(ow, p_wr + WR_O, DD * DD);
    round_tf32_kernel<<<(EE * MH * DD) / 4096, 256>>>(ew1, p_wr + WR_E1, EE * MH * DD);
    round_tf32_kernel<<<(EE * MH * DD) / 4096, 256>>>(ew2, p_wr + WR_E2, EE * MH * DD);
    concat_bias_kernel<<<(DD + 255) / 256, 256>>>(qb, kb, vb);

    // 1) decomposition (smem-tiled): Tr + S
    decomp_kernel<<<dim3(DD / 32, NN_SEQ / DNT, BB), 256>>>(
        x, alpha, dw7, dw25, dw49);

    // 1b) LN1 on S -> Sn (tf32-rounded only)
    ln_kernel<<<BB * NN_SEQ, 256>>>(p_S, n1g, n1b, nullptr, p_Sn);

    // 2) fused QKV projection -> g_qkv [T, 3072], rounded (mode 3)
    gemm_tf32<<<dim3(3 * DD / 128, TT / 128), 256, GSMEM>>>(
        p_Sn, p_wr + WR_Q, p_qkvb, nullptr, p_qkv, TT, 3 * DD, DD, 3,
        nullptr, nullptr, nullptr);

    // 3) ALiBi attention: TF32 mma flash tiles
    attn_mma_kernel<<<dim3(BB * HH, NN_SEQ / 128), 256, ATT_SMEM>>>(p_qkv, p_y);

    // 4) output projection fused with residual: x_s = S + (y @ ow^T + ob)
    dim3 gQ(DD / 128, TT / 128);
    gemm_tf32<<<gQ, 256, GSMEM>>>(p_y, p_wr + WR_O, ob, p_S, p_xs, TT, DD, DD, 0,
                                  nullptr, nullptr, nullptr);

    // 5) LN2 -> xf (exact) + xfr (rounded)
    ln_kernel<<<BB * NN_SEQ, 256>>>(p_xs, n2g, n2b, p_xf, p_xfr);

    // 6) router, token lists, aux
    router_kernel<<<TT, 128>>>(p_xf, rw);
    clear_cnt_kernel<<<1, 32>>>();
    build_lists_kernel<<<TT / 256, 256>>>();
    aux_reduce_kernel<<<1, 256>>>();

    // 7) sparse MoE: gather -> GEMM1(gelu, rounded h) -> GEMM2(scatter +=)
    dim3 gE1(MH / 128, TT / 128);
    dim3 gE2(DD / 128, TT / 128);
    for (int e = 0; e < EE; e++) {
        gemm_tf32<<<gE1, 256, GSMEM>>>(p_xfr, p_wr + WR_E1 + (size_t)e * MH * DD,
                                       eb1 + (size_t)e * MH,
                                       nullptr, p_h, TT, MH, DD, 1,
                                       p_list + e * TT, p_cnt + e, nullptr);
        gemm_tf32<<<gE2, 256, GSMEM>>>(p_h, p_wr + WR_E2 + (size_t)e * DD * MH,
                                       eb2 + (size_t)e * DD,
                                       nullptr, p_xs, TT, DD, MH, 2,
                                       p_list + e * TT, p_cnt + e, p_lw + e * TT);
    }

    // 8) trend conv + final sum + aux scalar
    int write_aux = (out_size > BB * NN_SEQ * DD) ? 1 : 0;
    final_kernel<<<BB * NN_SEQ, 256>>>(tw, tb, out, write_aux);
}

// round 14
// speedup vs baseline: 1.8157x; 1.4892x over previous
#include <cuda_runtime.h>
#include <cuda_bf16.h>
#include <math.h>
#include <stdint.h>

#define BB 8
#define NN_SEQ 1024
#define DD 1024
#define HH 16
#define DH 64
#define TT (BB * NN_SEQ)      // 8192 tokens
#define EE 4
#define MH 2048
#define LN_EPS 1e-5f

// ---------------- scratch (device globals; no allocations allowed) ----------
__device__ float g_Tr[BB * NN_SEQ * DD];
__device__ float g_S [BB * NN_SEQ * DD];
__device__ __nv_bfloat16 g_Snh[BB * NN_SEQ * DD];   // bf16 LN1 out (GEMM A)
__device__ float g_qkv[TT * 3 * DD];                // f32 (tf32-rounded) for attention
__device__ __nv_bfloat16 g_yh[BB * NN_SEQ * DD];    // bf16 attention out (GEMM A)
__device__ float g_xs[BB * NN_SEQ * DD];
__device__ float g_xf[BB * NN_SEQ * DD];            // exact (router input)
__device__ __nv_bfloat16 g_xfh[BB * NN_SEQ * DD];   // bf16 LN2 out (GEMM A)
__device__ __nv_bfloat16 g_hh[TT * MH];             // bf16 expert hidden
__device__ float g_gates[TT * EE];
__device__ float g_wts  [TT * EE];
__device__ int   g_list [EE * TT];
__device__ float g_lw   [EE * TT];
__device__ int   g_cnt  [EE];
__device__ float g_auxval[1];
__device__ float g_qkvb[3 * DD];
// bf16 weights: qw,kw,vw (stacked for fused QKV), ow, ew1, ew2
#define WR_Q  0
#define WR_K  (DD * DD)
#define WR_V  (2 * DD * DD)
#define WR_O  (3 * DD * DD)
#define WR_E1 (4 * DD * DD)
#define WR_E2 (4 * DD * DD + EE * MH * DD)
#define WR_TOTAL (4 * DD * DD + 2 * EE * MH * DD)
__device__ __nv_bfloat16 g_wh[WR_TOTAL];

// ---------------- rounding helpers ------------------------------------------
__device__ __forceinline__ uint32_t f2tf(float f) {
    uint32_t u;
    asm("cvt.rna.tf32.f32 %0, %1;" : "=r"(u) : "f"(f));
    return u;
}
__device__ __forceinline__ float tf32r(float f) {
    return __uint_as_float(f2tf(f));
}

// f32 -> bf16 weight conversion, 8 elems/thread
__global__ __launch_bounds__(256) void round_bf16_kernel(
    const float* __restrict__ src, __nv_bfloat16* __restrict__ dst, int n)
{
    int i = (blockIdx.x * 256 + threadIdx.x) * 8;
    if (i < n) {
        float4 a = *(const float4*)&src[i];
        float4 b = *(const float4*)&src[i + 4];
        __nv_bfloat162 o0 = make_bfloat162(__float2bfloat16_rn(a.x), __float2bfloat16_rn(a.y));
        __nv_bfloat162 o1 = make_bfloat162(__float2bfloat16_rn(a.z), __float2bfloat16_rn(a.w));
        __nv_bfloat162 o2 = make_bfloat162(__float2bfloat16_rn(b.x), __float2bfloat16_rn(b.y));
        __nv_bfloat162 o3 = make_bfloat162(__float2bfloat16_rn(b.z), __float2bfloat16_rn(b.w));
        uint4 pk;
        pk.x = *(uint32_t*)&o0; pk.y = *(uint32_t*)&o1;
        pk.z = *(uint32_t*)&o2; pk.w = *(uint32_t*)&o3;
        *(uint4*)&dst[i] = pk;
    }
}

__global__ __launch_bounds__(256) void concat_bias_kernel(
    const float* __restrict__ qb, const float* __restrict__ kb,
    const float* __restrict__ vb)
{
    int i = blockIdx.x * 256 + threadIdx.x;
    if (i < DD) {
        g_qkvb[i] = qb[i];
        g_qkvb[DD + i] = kb[i];
        g_qkvb[2 * DD + i] = vb[i];
    }
}

// ---------------- decomposition: smem-tiled depthwise convs -----------------
#define DNT 128
#define DHALO 24
#define DROWS (DNT + 2 * DHALO)   // 176
__global__ __launch_bounds__(256) void decomp_kernel(
    const float* __restrict__ x, const float* __restrict__ alpha,
    const float* __restrict__ dw7, const float* __restrict__ dw25,
    const float* __restrict__ dw49)
{
    __shared__ float xs[DROWS][32];
    int d0 = blockIdx.x * 32;
    int n0 = blockIdx.y * DNT;
    int b  = blockIdx.z;
    int tid = threadIdx.x;
    int d = tid & 31, nr = tid >> 5;

    float a0 = alpha[0], a1 = alpha[1], a2 = alpha[2];
    float mx = fmaxf(a0, fmaxf(a1, a2));
    float e0 = __expf(a0 - mx), e1 = __expf(a1 - mx), e2 = __expf(a2 - mx);
    float inv = 1.0f / (e0 + e1 + e2);
    float w0 = e0 * inv, w1 = e1 * inv, w2 = e2 * inv;

    const float* xb = x + (size_t)b * NN_SEQ * DD + d0 + d;
    for (int i = nr; i < DROWS; i += 8) {
        int idx = n0 - DHALO + i;
        idx = idx < 0 ? -idx : idx;
        idx = idx >= NN_SEQ ? (2 * NN_SEQ - 2 - idx) : idx;
        xs[i][d] = xb[(size_t)idx * DD];
    }

    int dg = d0 + d;
    float w7r[7], w25r[25], w49r[49];
#pragma unroll
    for (int j = 0; j < 7; j++)  w7r[j]  = dw7 [dg * 7  + j];
#pragma unroll
    for (int j = 0; j < 25; j++) w25r[j] = dw25[dg * 25 + j];
#pragma unroll
    for (int j = 0; j < 49; j++) w49r[j] = dw49[dg * 49 + j];
    __syncthreads();

    for (int jo = 0; jo < 16; jo++) {
        int nl = nr + 8 * jo;
        float t7 = 0.f, t25 = 0.f, t49 = 0.f;
#pragma unroll
        for (int j = 0; j < 7; j++)  t7  += w7r[j]  * xs[nl + 21 + j][d];
#pragma unroll
        for (int j = 0; j < 25; j++) t25 += w25r[j] * xs[nl + 12 + j][d];
#pragma unroll
        for (int j = 0; j < 49; j++) t49 += w49r[j] * xs[nl + j][d];
        float tr = w0 * t7 + w1 * t25 + w2 * t49;
        float sv = xs[nl + 24][d] - tr;
        size_t off = ((size_t)(b * NN_SEQ + n0 + nl)) * DD + dg;
        g_Tr[off] = tr;
        g_S [off] = sv;
    }
}

// ---------------- generic LN kernel (nullable f32 + bf16 outputs) -----------
__global__ __launch_bounds__(256) void ln_kernel(
    const float* __restrict__ in, const float* __restrict__ g,
    const float* __restrict__ bta, float* __restrict__ out,
    __nv_bfloat16* __restrict__ out_h)
{
    int bn = blockIdx.x;
    int tid = threadIdx.x;
    const float* row = in + (size_t)bn * DD;
    float v[4]; float sum = 0.f, sumsq = 0.f;
#pragma unroll
    for (int i = 0; i < 4; i++) {
        v[i] = row[tid + i * 256];
        sum += v[i]; sumsq += v[i] * v[i];
    }
    __shared__ float sh1[256], sh2[256];
    sh1[tid] = sum; sh2[tid] = sumsq;
    __syncthreads();
    for (int o = 128; o > 0; o >>= 1) {
        if (tid < o) { sh1[tid] += sh1[tid + o]; sh2[tid] += sh2[tid + o]; }
        __syncthreads();
    }
    float mean = sh1[0] * (1.0f / DD);
    float var  = sh2[0] * (1.0f / DD) - mean * mean;
    float rstd = rsqrtf(var + LN_EPS);
#pragma unroll
    for (int i = 0; i < 4; i++) {
        int d = tid + i * 256;
        float ov = (v[i] - mean) * rstd * g[d] + bta[d];
        if (out)   out[(size_t)bn * DD + d] = ov;
        if (out_h) out_h[(size_t)bn * DD + d] = __float2bfloat16_rn(ov);
    }
}

// ---------------- BF16 tensor-core NT GEMM, cp.async 3-stage pipeline -------
// C[M,Nn] = A[M,K] @ W[Nn,K]^T, A/W bf16, f32 accumulate.
// Same word-level smem layout + swizzle as the tf32 version; each b32 word
// holds a bf16 pair; k-tile = 64 elements (128 B/row); m16n8k16 fragments
// use the SAME word indices (sw0/sw1) as m16n8k8 tf32.
// mode 0: C(f32) = acc + bias (+ addend)
// mode 3: C(f32) = tf32r(acc + bias)
// mode 1: C(bf16)[row] = gelu(acc+bias), A rows gathered via rowidx, row<cnt
// mode 2: C(f32)[rowidx[row]] += (acc + bias) * rowsw[row], row<cnt
__device__ __forceinline__ void mma_bf16(float* d, const uint32_t* a, const uint32_t* b) {
    asm volatile(
        "mma.sync.aligned.m16n8k16.row.col.f32.bf16.bf16.f32 "
        "{%0,%1,%2,%3}, {%4,%5,%6,%7}, {%8,%9}, {%0,%1,%2,%3};"
        : "+f"(d[0]), "+f"(d[1]), "+f"(d[2]), "+f"(d[3])
        : "r"(a[0]), "r"(a[1]), "r"(a[2]), "r"(a[3]),
          "r"(b[0]), "r"(b[1]));
}

__device__ __forceinline__ void cpa16(float* dst, const void* src) {
    uint32_t d = (uint32_t)__cvta_generic_to_shared(dst);
    asm volatile("cp.async.cg.shared.global [%0], [%1], 16;\n" :: "r"(d), "l"(src));
}

#define GSTG 3
#define GSMEM (GSTG * 4096 * 2 * (int)sizeof(float))   // 96 KB
__global__ __launch_bounds__(256, 2) void gemm_bf16(
    const __nv_bfloat16* __restrict__ A, const __nv_bfloat16* __restrict__ W,
    const float* __restrict__ bias, const float* __restrict__ addend,
    void* __restrict__ Cv, int M, int Nn, int K, int mode,
    const int* __restrict__ rowidx, const int* __restrict__ cnt_ptr,
    const float* __restrict__ rowsw)
{
    int m0 = blockIdx.y * 128, n0 = blockIdx.x * 128;
    int cval = cnt_ptr ? *cnt_ptr : M;
    if (m0 >= cval) return;

    extern __shared__ float sm[];
    float* Abuf = sm;                    // [GSTG][4096] words
    float* Wbuf = sm + GSTG * 4096;

    int tid = threadIdx.x;
    int lrow = tid >> 1;
    int cbase = (tid & 1) * 4;           // 16B-chunk base within 128B row

    int arow = m0 + lrow;
    if (mode == 1 && rowidx) arow = rowidx[arow < cval ? arow : (cval - 1)];
    const __nv_bfloat16* Aptr = A + (size_t)arow * K + cbase * 8;
    const __nv_bfloat16* Wptr = W + (size_t)(n0 + lrow) * K + cbase * 8;

    int dsts[4];
#pragma unroll
    for (int j = 0; j < 4; j++)
        dsts[j] = lrow * 32 + ((cbase + j) ^ (lrow & 7)) * 4;

    int lane = tid & 31, wid = tid >> 5;
    int wm = wid >> 2, wn = wid & 3;
    int g = lane >> 2, c = lane & 3;

    float acc[4][4][4];
#pragma unroll
    for (int i = 0; i < 4; i++)
#pragma unroll
        for (int j = 0; j < 4; j++)
#pragma unroll
            for (int r = 0; r < 4; r++) acc[i][j][r] = 0.f;

    int nk = K / 64;
#pragma unroll
    for (int st = 0; st < 2; st++) {
        if (st < nk) {
            int k0 = st * 64;
#pragma unroll
            for (int j = 0; j < 4; j++) {
                cpa16(Abuf + st * 4096 + dsts[j], Aptr + k0 + j * 8);
                cpa16(Wbuf + st * 4096 + dsts[j], Wptr + k0 + j * 8);
            }
            asm volatile("cp.async.commit_group;\n" ::);
        }
    }

    for (int it = 0; it < nk; it++) {
        if (it < nk - 1)
            asm volatile("cp.async.wait_group 1;\n" ::);
        else
            asm volatile("cp.async.wait_group 0;\n" ::);
        __syncthreads();

        int pf = it + 2;
        if (pf < nk) {
            int st = pf % GSTG;
            int k0 = pf * 64;
#pragma unroll
            for (int j = 0; j < 4; j++) {
                cpa16(Abuf + st * 4096 + dsts[j], Aptr + k0 + j * 8);
                cpa16(Wbuf + st * 4096 + dsts[j], Wptr + k0 + j * 8);
            }
            asm volatile("cp.async.commit_group;\n" ::);
        }

        const float* Ab = Abuf + (it % GSTG) * 4096;
        const float* Wb = Wbuf + (it % GSTG) * 4096;
#pragma unroll
        for (int s = 0; s < 4; s++) {          // 4 x k16 = 64 k
            int sw0 = ((2 * s) ^ g) * 4 + c;
            int sw1 = ((2 * s + 1) ^ g) * 4 + c;
            uint32_t af[4][4], bf[4][2];
#pragma unroll
            for (int mf = 0; mf < 4; mf++) {
                const float* pa = Ab + (wm * 64 + mf * 16 + g) * 32;
                af[mf][0] = __float_as_uint(pa[sw0]);
                af[mf][1] = __float_as_uint(pa[8 * 32 + sw0]);
                af[mf][2] = __float_as_uint(pa[sw1]);
                af[mf][3] = __float_as_uint(pa[8 * 32 + sw1]);
            }
#pragma unroll
            for (int nf = 0; nf < 4; nf++) {
                const float* pw = Wb + (wn * 32 + nf * 8 + g) * 32;
                bf[nf][0] = __float_as_uint(pw[sw0]);
                bf[nf][1] = __float_as_uint(pw[sw1]);
            }
#pragma unroll
            for (int mf = 0; mf < 4; mf++)
#pragma unroll
                for (int nf = 0; nf < 4; nf++)
                    mma_bf16(acc[mf][nf], af[mf], bf[nf]);
        }
    }

    float* C = (float*)Cv;
    __nv_bfloat16* Cb = (__nv_bfloat16*)Cv;
#pragma unroll
    for (int mf = 0; mf < 4; mf++) {
#pragma unroll
        for (int half = 0; half < 2; half++) {
            int r = m0 + wm * 64 + mf * 16 + g + half * 8;
#pragma unroll
            for (int nf = 0; nf < 4; nf++) {
                int col = n0 + wn * 32 + nf * 8 + 2 * c;
                float v0 = acc[mf][nf][half * 2 + 0];
                float v1 = acc[mf][nf][half * 2 + 1];
                if (bias) { v0 += bias[col]; v1 += bias[col + 1]; }
                if (mode == 0 || mode == 3) {
                    size_t off = (size_t)r * Nn + col;
                    if (addend) {
                        float2 ad = *(const float2*)&addend[off];
                        v0 += ad.x; v1 += ad.y;
                    }
                    float2 ov = (mode == 3)
                        ? make_float2(tf32r(v0), tf32r(v1))
                        : make_float2(v0, v1);
                    *(float2*)&C[off] = ov;
                } else if (mode == 1) {
                    if (r < cval) {
                        float g0 = 0.5f * v0 * (1.0f + erff(v0 * 0.70710678118f));
                        float g1 = 0.5f * v1 * (1.0f + erff(v1 * 0.70710678118f));
                        __nv_bfloat162 ov = make_bfloat162(
                            __float2bfloat16_rn(g0), __float2bfloat16_rn(g1));
                        *(__nv_bfloat162*)&Cb[(size_t)r * Nn + col] = ov;
                    }
                } else {
                    if (r < cval) {
                        int tok = rowidx[r];
                        float w = rowsw[r];
                        size_t off = (size_t)tok * Nn + col;
                        float2 old = *(const float2*)&C[off];
                        float2 ov = make_float2(old.x + v0 * w, old.y + v1 * w);
                        *(float2*)&C[off] = ov;
                    }
                }
            }
        }
    }
}

// ---------------- attention: TF32 mma flash, 128q x (b,h) per block ---------
#define ATT_SMEM ((4096 + 4096 + 8192) * (int)sizeof(float))
__global__ __launch_bounds__(256) void attn_mma_kernel(
    const float* __restrict__ qkv, __nv_bfloat16* __restrict__ y)
{
    extern __shared__ float sm[];
    float* Ks = sm;
    float* Vt = sm + 4096;
    float* Ps = sm + 8192;

    int bh = blockIdx.x;
    int b = bh >> 4, h = bh & 15;
    int q0 = blockIdx.y * 128;
    int tid = threadIdx.x, lane = tid & 31, wid = tid >> 5;
    int g = lane >> 2, c = lane & 3;
    int qb = wid * 16;
    float slope = exp2f(-0.5f * (float)(h + 1));

    const float* qkvb = qkv + (size_t)(b * NN_SEQ) * (3 * DD);

    for (int i = tid; i < 128 * 16; i += 256) {
        int r = i >> 4, ch = i & 15;
        float4 v = *(const float4*)&qkvb[(size_t)(q0 + r) * (3 * DD) + h * DH + ch * 4];
        *(float4*)&Ps[r * 64 + ((ch ^ (r & 7)) << 2)] = v;
    }
    __syncthreads();

    uint32_t qf[8][4];
#pragma unroll
    for (int s = 0; s < 8; s++) {
        const float* p0 = &Ps[(qb + g) * 64];
        const float* p1 = &Ps[(qb + 8 + g) * 64];
        int sw0 = (((2 * s) ^ g) << 2) + c;
        int sw1 = (((2 * s + 1) ^ g) << 2) + c;
        qf[s][0] = __float_as_uint(p0[sw0] * 0.125f);
        qf[s][1] = __float_as_uint(p1[sw0] * 0.125f);
        qf[s][2] = __float_as_uint(p0[sw1] * 0.125f);
        qf[s][3] = __float_as_uint(p1[sw1] * 0.125f);
    }

    float oa[8][4];
#pragma unroll
    for (int i = 0; i < 8; i++)
#pragma unroll
        for (int j = 0; j < 4; j++) oa[i][j] = 0.f;
    float m_lo = -1e30f, m_hi = -1e30f, l_lo = 0.f, l_hi = 0.f;
    int qlo = q0 + qb + g, qhi = qlo + 8;

    for (int kt = 0; kt < NN_SEQ; kt += 64) {
        __syncthreads();
        for (int i = tid; i < 64 * 16; i += 256) {
            int r = i >> 4, ch = i & 15;
            size_t rowoff = (size_t)(kt + r) * (3 * DD) + h * DH + ch * 4;
            int dst = r * 64 + ((ch ^ (r & 7)) << 2);
            *(float4*)&Ks[dst] = *(const float4*)&qkvb[DD + rowoff];
            *(float4*)&Ps[dst] = *(const float4*)&qkvb[2 * DD + rowoff];
        }
        __syncthreads();

        {
            int d = tid & 63, kg = tid >> 6;
#pragma unroll
            for (int i = 0; i < 16; i++) {
                int kk = kg * 16 + i;
                float v = Ps[kk * 64 + (((d >> 2) ^ (kk & 7)) << 2) + (d & 3)];
                Vt[d * 64 + (((kk >> 2) ^ (d & 7)) << 2) + (kk & 3)] = v;
            }
        }

        float sa[8][4];
#pragma unroll
        for (int i = 0; i < 8; i++)
#pragma unroll
            for (int j = 0; j < 4; j++) sa[i][j] = 0.f;
#pragma unroll
        for (int s = 0; s < 8; s++) {
            int sw0 = (((2 * s) ^ g) << 2) + c;
            int sw1 = (((2 * s + 1) ^ g) << 2) + c;
#pragma unroll
            for (int nt = 0; nt < 8; nt++) {
                const float* pk = &Ks[(nt * 8 + g) * 64];
                uint32_t bfr[2];
                bfr[0] = __float_as_uint(pk[sw0]);
                bfr[1] = __float_as_uint(pk[sw1]);
                asm volatile(
                    "mma.sync.aligned.m16n8k8.row.col.f32.tf32.tf32.f32 "
                    "{%0,%1,%2,%3}, {%4,%5,%6,%7}, {%8,%9}, {%0,%1,%2,%3};"
                    : "+f"(sa[nt][0]), "+f"(sa[nt][1]), "+f"(sa[nt][2]), "+f"(sa[nt][3])
                    : "r"(qf[s][0]), "r"(qf[s][1]), "r"(qf[s][2]), "r"(qf[s][3]),
                      "r"(bfr[0]), "r"(bfr[1]));
            }
        }
        __syncthreads();

        float mx_lo = -1e30f, mx_hi = -1e30f;
#pragma unroll
        for (int nt = 0; nt < 8; nt++) {
            int k0 = kt + nt * 8 + 2 * c;
            float d0 = (k0 > qlo) ? (float)(k0 - qlo) : 0.f;
            float d1 = (k0 + 1 > qlo) ? (float)(k0 + 1 - qlo) : 0.f;
            float d2 = (k0 > qhi) ? (float)(k0 - qhi) : 0.f;
            float d3 = (k0 + 1 > qhi) ? (float)(k0 + 1 - qhi) : 0.f;
            sa[nt][0] -= slope * d0; sa[nt][1] -= slope * d1;
            sa[nt][2] -= slope * d2; sa[nt][3] -= slope * d3;
            mx_lo = fmaxf(mx_lo, fmaxf(sa[nt][0], sa[nt][1]));
            mx_hi = fmaxf(mx_hi, fmaxf(sa[nt][2], sa[nt][3]));
        }
        mx_lo = fmaxf(mx_lo, __shfl_xor_sync(0xffffffffu, mx_lo, 1));
        mx_lo = fmaxf(mx_lo, __shfl_xor_sync(0xffffffffu, mx_lo, 2));
        mx_hi = fmaxf(mx_hi, __shfl_xor_sync(0xffffffffu, mx_hi, 1));
        mx_hi = fmaxf(mx_hi, __shfl_xor_sync(0xffffffffu, mx_hi, 2));
        float mn_lo = fmaxf(m_lo, mx_lo), mn_hi = fmaxf(m_hi, mx_hi);
        float cc_lo = __expf(m_lo - mn_lo), cc_hi = __expf(m_hi - mn_hi);
        m_lo = mn_lo; m_hi = mn_hi;

        float rs_lo = 0.f, rs_hi = 0.f;
#pragma unroll
        for (int nt = 0; nt < 8; nt++) {
            float p0 = __expf(sa[nt][0] - mn_lo), p1 = __expf(sa[nt][1] - mn_lo);
            float p2 = __expf(sa[nt][2] - mn_hi), p3 = __expf(sa[nt][3] - mn_hi);
            rs_lo += p0 + p1; rs_hi += p2 + p3;
            int col = nt * 8 + 2 * c;
            int ch = col >> 2, off = col & 3;
            *(float2*)&Ps[(qb + g) * 64 + ((ch ^ g) << 2) + off] =
                make_float2(tf32r(p0), tf32r(p1));
            *(float2*)&Ps[(qb + 8 + g) * 64 + ((ch ^ g) << 2) + off] =
                make_float2(tf32r(p2), tf32r(p3));
        }
        rs_lo += __shfl_xor_sync(0xffffffffu, rs_lo, 1);
        rs_lo += __shfl_xor_sync(0xffffffffu, rs_lo, 2);
        rs_hi += __shfl_xor_sync(0xffffffffu, rs_hi, 1);
        rs_hi += __shfl_xor_sync(0xffffffffu, rs_hi, 2);
        l_lo = l_lo * cc_lo + rs_lo;
        l_hi = l_hi * cc_hi + rs_hi;
#pragma unroll
        for (int nt = 0; nt < 8; nt++) {
            oa[nt][0] *= cc_lo; oa[nt][1] *= cc_lo;
            oa[nt][2] *= cc_hi; oa[nt][3] *= cc_hi;
        }
        __syncwarp();

#pragma unroll
        for (int s2 = 0; s2 < 8; s2++) {
            int sw0 = (((2 * s2) ^ g) << 2) + c;
            int sw1 = (((2 * s2 + 1) ^ g) << 2) + c;
            const float* pl = &Ps[(qb + g) * 64];
            const float* ph = &Ps[(qb + 8 + g) * 64];
            uint32_t af[4];
            af[0] = __float_as_uint(pl[sw0]);
            af[1] = __float_as_uint(ph[sw0]);
            af[2] = __float_as_uint(pl[sw1]);
            af[3] = __float_as_uint(ph[sw1]);
#pragma unroll
            for (int nt = 0; nt < 8; nt++) {
                const float* pv = &Vt[(nt * 8 + g) * 64];
                uint32_t bfr[2];
                bfr[0] = __float_as_uint(pv[sw0]);
                bfr[1] = __float_as_uint(pv[sw1]);
                asm volatile(
                    "mma.sync.aligned.m16n8k8.row.col.f32.tf32.tf32.f32 "
                    "{%0,%1,%2,%3}, {%4,%5,%6,%7}, {%8,%9}, {%0,%1,%2,%3};"
                    : "+f"(oa[nt][0]), "+f"(oa[nt][1]), "+f"(oa[nt][2]), "+f"(oa[nt][3])
                    : "r"(af[0]), "r"(af[1]), "r"(af[2]), "r"(af[3]),
                      "r"(bfr[0]), "r"(bfr[1]));
            }
        }
    }

    float il_lo = 1.0f / l_lo, il_hi = 1.0f / l_hi;
#pragma unroll
    for (int nt = 0; nt < 8; nt++) {
        int col = h * DH + nt * 8 + 2 * c;
        size_t rlo = (size_t)(b * NN_SEQ + qlo) * DD + col;
        __nv_bfloat162 o0 = make_bfloat162(
            __float2bfloat16_rn(oa[nt][0] * il_lo),
            __float2bfloat16_rn(oa[nt][1] * il_lo));
        __nv_bfloat162 o1 = make_bfloat162(
            __float2bfloat16_rn(oa[nt][2] * il_hi),
            __float2bfloat16_rn(oa[nt][3] * il_hi));
        *(__nv_bfloat162*)&y[rlo] = o0;
        *(__nv_bfloat162*)&y[rlo + 8 * DD] = o1;
    }
}

// ---------------- router: gates + top-2 weights -----------------------------
__global__ __launch_bounds__(128) void router_kernel(
    const float* __restrict__ xf, const float* __restrict__ rw)
{
    int t = blockIdx.x;
    int lane = threadIdx.x & 31, wrp = threadIdx.x >> 5;
    const float* xr = xf + (size_t)t * DD;
    const float* wr = rw + (size_t)wrp * DD;
    float s = 0.f;
    for (int i = lane; i < DD; i += 32) s += xr[i] * wr[i];
#pragma unroll
    for (int o = 16; o > 0; o >>= 1) s += __shfl_xor_sync(0xffffffffu, s, o);
    __shared__ float sh[4];
    if (lane == 0) sh[wrp] = s;
    __syncthreads();
    if (threadIdx.x == 0) {
        float g[4]; float mx = -1e30f;
#pragma unroll
        for (int e = 0; e < EE; e++) { g[e] = sh[e]; mx = fmaxf(mx, g[e]); }
        float sum = 0.f;
#pragma unroll
        for (int e = 0; e < EE; e++) { g[e] = __expf(g[e] - mx); sum += g[e]; }
        float inv = 1.0f / sum;
#pragma unroll
        for (int e = 0; e < EE; e++) { g[e] *= inv; g_gates[t * EE + e] = g[e]; }
        int i1 = 0;
#pragma unroll
        for (int e = 1; e < EE; e++) if (g[e] > g[i1]) i1 = e;
        int i2 = -1;
#pragma unroll
        for (int e = 0; e < EE; e++)
            if (e != i1 && (i2 < 0 || g[e] > g[i2])) i2 = e;
        float norm = fmaxf(g[i1] + g[i2], 1e-9f);
        float w4[4] = {0.f, 0.f, 0.f, 0.f};
        w4[i1] = g[i1] / norm;
        w4[i2] = g[i2] / norm;
#pragma unroll
        for (int e = 0; e < EE; e++) g_wts[t * EE + e] = w4[e];
    }
}

// ---------------- expert token lists ----------------------------------------
__global__ void clear_cnt_kernel() {
    if (threadIdx.x < EE) g_cnt[threadIdx.x] = 0;
}

__global__ __launch_bounds__(256) void build_lists_kernel() {
    int t = blockIdx.x * 256 + threadIdx.x;
    if (t >= TT) return;
#pragma unroll
    for (int e = 0; e < EE; e++) {
        float w = g_wts[t * EE + e];
        if (w > 0.f) {
            int p = atomicAdd(&g_cnt[e], 1);
            g_list[e * TT + p] = t;
            g_lw[e * TT + p] = w;
        }
    }
}

// ---------------- deterministic aux reduction -------------------------------
__global__ __launch_bounds__(256) void aux_reduce_kernel()
{
    int tid = threadIdx.x;
    float sg[EE] = {0.f, 0.f, 0.f, 0.f};
    float sc[EE] = {0.f, 0.f, 0.f, 0.f};
    for (int t = tid; t < TT; t += 256) {
#pragma unroll
        for (int e = 0; e < EE; e++) {
            sg[e] += g_gates[t * EE + e];
            sc[e] += (g_wts[t * EE + e] > 0.f) ? 1.f : 0.f;
        }
    }
    __shared__ float sh[256];
    float aux = 0.f;
#pragma unroll
    for (int e = 0; e < EE; e++) {
        sh[tid] = sg[e]; __syncthreads();
        for (int o = 128; o > 0; o >>= 1) {
            if (tid < o) sh[tid] += sh[tid + o];
            __syncthreads();
        }
        float tot_g = sh[0]; __syncthreads();
        sh[tid] = sc[e]; __syncthreads();
        for (int o = 128; o > 0; o >>= 1) {
            if (tid < o) sh[tid] += sh[tid + o];
            __syncthreads();
        }
        float tot_c = sh[0]; __syncthreads();
        aux += (tot_g / (float)TT) * (tot_c / (float)TT);
    }
    if (tid == 0) g_auxval[0] = (float)EE * aux;
}

// ---------------- final: + trend depthwise conv(k=5) + aux ------------------
__global__ __launch_bounds__(256) void final_kernel(
    const float* __restrict__ tw, const float* __restrict__ tb,
    float* __restrict__ out, int write_aux)
{
    int bn = blockIdx.x;
    int b = bn / NN_SEQ, n = bn % NN_SEQ;
    int tid = threadIdx.x;
#pragma unroll
    for (int i = 0; i < 4; i++) {
        int d = tid + i * 256;
        float vsum = g_xs[(size_t)bn * DD + d] + tb[d];
#pragma unroll
        for (int j = 0; j < 5; j++) {
            int nn = n - 2 + j;
            if (nn >= 0 && nn < NN_SEQ)
                vsum += tw[d * 5 + j] * g_Tr[((size_t)b * NN_SEQ + nn) * DD + d];
        }
        out[(size_t)bn * DD + d] = vsum;
    }
    if (bn == 0 && tid == 0 && write_aux)
        out[(size_t)BB * NN_SEQ * DD] = g_auxval[0];
}

// ---------------- host orchestration ---------------------------------------
extern "C" void kernel_launch(void* const* d_in, const int* in_sizes, int n_in,
                              void* d_out, int out_size)
{
    const float* x    = (const float*)d_in[0];
    const float* qw   = (const float*)d_in[1];
    const float* qb   = (const float*)d_in[2];
    const float* kw   = (const float*)d_in[3];
    const float* kb   = (const float*)d_in[4];
    const float* vw   = (const float*)d_in[5];
    const float* vb   = (const float*)d_in[6];
    const float* ow   = (const float*)d_in[7];
    const float* ob   = (const float*)d_in[8];
    const float* n1g  = (const float*)d_in[9];
    const float* n1b  = (const float*)d_in[10];
    const float* n2g  = (const float*)d_in[11];
    const float* n2b  = (const float*)d_in[12];
    const float* alpha= (const float*)d_in[13];
    const float* dw7  = (const float*)d_in[14];
    const float* dw25 = (const float*)d_in[15];
    const float* dw49 = (const float*)d_in[16];
    const float* rw   = (const float*)d_in[17];
    const float* ew1  = (const float*)d_in[18];
    const float* eb1  = (const float*)d_in[19];
    const float* ew2  = (const float*)d_in[20];
    const float* eb2  = (const float*)d_in[21];
    const float* tw   = (const float*)d_in[22];
    const float* tb   = (const float*)d_in[23];
    float* out = (float*)d_out;

    float *p_qkv, *p_xs, *p_xf, *p_S, *p_lw, *p_qkvb;
    __nv_bfloat16 *p_Snh, *p_yh, *p_xfh, *p_hh, *p_wh;
    int *p_list, *p_cnt;
    cudaGetSymbolAddress((void**)&p_Snh, g_Snh);
    cudaGetSymbolAddress((void**)&p_qkv, g_qkv);
    cudaGetSymbolAddress((void**)&p_yh,  g_yh);
    cudaGetSymbolAddress((void**)&p_xs, g_xs);
    cudaGetSymbolAddress((void**)&p_xf, g_xf);
    cudaGetSymbolAddress((void**)&p_xfh, g_xfh);
    cudaGetSymbolAddress((void**)&p_hh,  g_hh);
    cudaGetSymbolAddress((void**)&p_S,  g_S);
    cudaGetSymbolAddress((void**)&p_lw,  g_lw);
    cudaGetSymbolAddress((void**)&p_list, g_list);
    cudaGetSymbolAddress((void**)&p_cnt,  g_cnt);
    cudaGetSymbolAddress((void**)&p_wh,  g_wh);
    cudaGetSymbolAddress((void**)&p_qkvb, g_qkvb);

    cudaFuncSetAttribute(attn_mma_kernel,
                         cudaFuncAttributeMaxDynamicSharedMemorySize, ATT_SMEM);
    cudaFuncSetAttribute(gemm_bf16,
                         cudaFuncAttributeMaxDynamicSharedMemorySize, GSMEM);

    // 0) weights -> bf16; concat QKV biases
    round_bf16_kernel<<<(DD * DD) / 2048, 256>>>(qw, p_wh + WR_Q, DD * DD);
    round_bf16_kernel<<<(DD * DD) / 2048, 256>>>(kw, p_wh + WR_K, DD * DD);
    round_bf16_kernel<<<(DD * DD) / 2048, 256>>>(vw, p_wh + WR_V, DD * DD);
    round_bf16_kernel<<<(DD * DD) / 2048, 256>>>(ow, p_wh + WR_O, DD * DD);
    round_bf16_kernel<<<(EE * MH * DD) / 2048, 256>>>(ew1, p_wh + WR_E1, EE * MH * DD);
    round_bf16_kernel<<<(EE * MH * DD) / 2048, 256>>>(ew2, p_wh + WR_E2, EE * MH * DD);
    concat_bias_kernel<<<(DD + 255) / 256, 256>>>(qb, kb, vb);

    // 1) decomposition (smem-tiled): Tr + S; then LN1 -> Snh (bf16)
    decomp_kernel<<<dim3(DD / 32, NN_SEQ / DNT, BB), 256>>>(
        x, alpha, dw7, dw25, dw49);
    ln_kernel<<<BB * NN_SEQ, 256>>>(p_S, n1g, n1b, nullptr, p_Snh);

    // 2) fused QKV projection (bf16) -> g_qkv f32 tf32-rounded (mode 3)
    gemm_bf16<<<dim3(3 * DD / 128, TT / 128), 256, GSMEM>>>(
        p_Snh, p_wh + WR_Q, p_qkvb, nullptr, p_qkv, TT, 3 * DD, DD, 3,
        nullptr, nullptr, nullptr);

    // 3) ALiBi attention (tf32 mma) -> y bf16
    attn_mma_kernel<<<dim3(BB * HH, NN_SEQ / 128), 256, ATT_SMEM>>>(p_qkv, p_yh);

    // 4) output projection (bf16) + residual: x_s = S + (y @ ow^T + ob)
    dim3 gQ(DD / 128, TT / 128);
    gemm_bf16<<<gQ, 256, GSMEM>>>(p_yh, p_wh + WR_O, ob, p_S, p_xs, TT, DD, DD, 0,
                                  nullptr, nullptr, nullptr);

    // 5) LN2 -> xf (exact f32) + xfh (bf16)
    ln_kernel<<<BB * NN_SEQ, 256>>>(p_xs, n2g, n2b, p_xf, p_xfh);

    // 6) router, token lists, aux
    router_kernel<<<TT, 128>>>(p_xf, rw);
    clear_cnt_kernel<<<1, 32>>>();
    build_lists_kernel<<<TT / 256, 256>>>();
    aux_reduce_kernel<<<1, 256>>>();

    // 7) sparse MoE (bf16): gather -> GEMM1(gelu -> h bf16) -> GEMM2(scatter)
    dim3 gE1(MH / 128, TT / 128);
    dim3 gE2(DD / 128, TT / 128);
    for (int e = 0; e < EE; e++) {
        gemm_bf16<<<gE1, 256, GSMEM>>>(p_xfh, p_wh + WR_E1 + (size_t)e * MH * DD,
                                       eb1 + (size_t)e * MH,
                                       nullptr, p_hh, TT, MH, DD, 1,
                                       p_list + e * TT, p_cnt + e, nullptr);
        gemm_bf16<<<gE2, 256, GSMEM>>>(p_hh, p_wh + WR_E2 + (size_t)e * DD * MH,
                                       eb2 + (size_t)e * DD,
                                       nullptr, p_xs, TT, DD, MH, 2,
                                       p_list + e * TT, p_cnt + e, p_lw + e * TT);
    }

    // 8) trend conv + final sum + aux scalar
    int write_aux = (out_size > BB * NN_SEQ * DD) ? 1 : 0;
    final_kernel<<<BB * NN_SEQ, 256>>>(tw, tb, out, write_aux);
}

// round 16
// speedup vs baseline: 1.9433x; 1.0703x over previous
#include <cuda_runtime.h>
#include <cuda_bf16.h>
#include <math.h>
#include <stdint.h>

#define BB 8
#define NN_SEQ 1024
#define DD 1024
#define HH 16
#define DH 64
#define TT (BB * NN_SEQ)      // 8192 tokens
#define EE 4
#define MH 2048
#define LN_EPS 1e-5f

// ---------------- scratch (device globals; no allocations allowed) ----------
__device__ float g_Tr[BB * NN_SEQ * DD];
__device__ float g_S [BB * NN_SEQ * DD];
__device__ __nv_bfloat16 g_Snh[BB * NN_SEQ * DD];
__device__ float g_qkv[TT * 3 * DD];
__device__ __nv_bfloat16 g_yh[BB * NN_SEQ * DD];
__device__ float g_xs[BB * NN_SEQ * DD];
__device__ float g_xf[BB * NN_SEQ * DD];
__device__ __nv_bfloat16 g_xfh[BB * NN_SEQ * DD];
__device__ __nv_bfloat16 g_hh[(size_t)EE * TT * MH];   // per-expert hidden
__device__ float g_gates[TT * EE];
__device__ float g_wts  [TT * EE];
__device__ int   g_list [EE * TT];
__device__ float g_lw   [EE * TT];
__device__ int   g_cnt  [EE];
__device__ float g_auxval[1];
__device__ float g_qkvb[3 * DD];
#define WR_Q  0
#define WR_K  (DD * DD)
#define WR_V  (2 * DD * DD)
#define WR_O  (3 * DD * DD)
#define WR_E1 (4 * DD * DD)
#define WR_E2 (4 * DD * DD + EE * MH * DD)
#define WR_TOTAL (4 * DD * DD + 2 * EE * MH * DD)
__device__ __nv_bfloat16 g_wh[WR_TOTAL];

// ---------------- rounding helpers ------------------------------------------
__device__ __forceinline__ uint32_t f2tf(float f) {
    uint32_t u;
    asm("cvt.rna.tf32.f32 %0, %1;" : "=r"(u) : "f"(f));
    return u;
}
__device__ __forceinline__ float tf32r(float f) {
    return __uint_as_float(f2tf(f));
}

__device__ __forceinline__ void bf16_pack8(const float* src, __nv_bfloat16* dst) {
    float4 a = *(const float4*)src;
    float4 b = *(const float4*)(src + 4);
    __nv_bfloat162 o0 = make_bfloat162(__float2bfloat16_rn(a.x), __float2bfloat16_rn(a.y));
    __nv_bfloat162 o1 = make_bfloat162(__float2bfloat16_rn(a.z), __float2bfloat16_rn(a.w));
    __nv_bfloat162 o2 = make_bfloat162(__float2bfloat16_rn(b.x), __float2bfloat16_rn(b.y));
    __nv_bfloat162 o3 = make_bfloat162(__float2bfloat16_rn(b.z), __float2bfloat16_rn(b.w));
    uint4 pk;
    pk.x = *(uint32_t*)&o0; pk.y = *(uint32_t*)&o1;
    pk.z = *(uint32_t*)&o2; pk.w = *(uint32_t*)&o3;
    *(uint4*)dst = pk;
}

// merged 3-source rounding (each source n_each elems, dst contiguous)
__global__ __launch_bounds__(256) void round_bf16_3_kernel(
    const float* __restrict__ s0, const float* __restrict__ s1,
    const float* __restrict__ s2, __nv_bfloat16* __restrict__ dst, int n_each)
{
    int i = (blockIdx.x * 256 + threadIdx.x) * 16;
    if (i >= 3 * n_each) return;
    int which = i / n_each;
    const float* src = which == 0 ? s0 : (which == 1 ? s1 : s2);
    int j = i - which * n_each;
    bf16_pack8(src + j, dst + i);
    bf16_pack8(src + j + 8, dst + i + 8);
}

__global__ __launch_bounds__(256) void round_bf16_2_kernel(
    const float* __restrict__ s0, const float* __restrict__ s1,
    __nv_bfloat16* __restrict__ dst, int n_each)
{
    int i = (blockIdx.x * 256 + threadIdx.x) * 16;
    if (i >= 2 * n_each) return;
    int which = i / n_each;
    const float* src = which == 0 ? s0 : s1;
    int j = i - which * n_each;
    bf16_pack8(src + j, dst + i);
    bf16_pack8(src + j + 8, dst + i + 8);
}

__global__ __launch_bounds__(256) void round_bf16_kernel(
    const float* __restrict__ src, __nv_bfloat16* __restrict__ dst, int n)
{
    int i = (blockIdx.x * 256 + threadIdx.x) * 16;
    if (i < n) {
        bf16_pack8(src + i, dst + i);
        bf16_pack8(src + i + 8, dst + i + 8);
    }
}

__global__ __launch_bounds__(256) void concat_bias_kernel(
    const float* __restrict__ qb, const float* __restrict__ kb,
    const float* __restrict__ vb)
{
    int i = blockIdx.x * 256 + threadIdx.x;
    if (i < DD) {
        g_qkvb[i] = qb[i];
        g_qkvb[DD + i] = kb[i];
        g_qkvb[2 * DD + i] = vb[i];
    }
}

// ---------------- decomposition: smem-tiled depthwise convs -----------------
#define DNT 128
#define DHALO 24
#define DROWS (DNT + 2 * DHALO)   // 176
__global__ __launch_bounds__(256) void decomp_kernel(
    const float* __restrict__ x, const float* __restrict__ alpha,
    const float* __restrict__ dw7, const float* __restrict__ dw25,
    const float* __restrict__ dw49)
{
    __shared__ float xs[DROWS][32];
    int d0 = blockIdx.x * 32;
    int n0 = blockIdx.y * DNT;
    int b  = blockIdx.z;
    int tid = threadIdx.x;
    int d = tid & 31, nr = tid >> 5;

    float a0 = alpha[0], a1 = alpha[1], a2 = alpha[2];
    float mx = fmaxf(a0, fmaxf(a1, a2));
    float e0 = __expf(a0 - mx), e1 = __expf(a1 - mx), e2 = __expf(a2 - mx);
    float inv = 1.0f / (e0 + e1 + e2);
    float w0 = e0 * inv, w1 = e1 * inv, w2 = e2 * inv;

    const float* xb = x + (size_t)b * NN_SEQ * DD + d0 + d;
    for (int i = nr; i < DROWS; i += 8) {
        int idx = n0 - DHALO + i;
        idx = idx < 0 ? -idx : idx;
        idx = idx >= NN_SEQ ? (2 * NN_SEQ - 2 - idx) : idx;
        xs[i][d] = xb[(size_t)idx * DD];
    }

    int dg = d0 + d;
    float w7r[7], w25r[25], w49r[49];
#pragma unroll
    for (int j = 0; j < 7; j++)  w7r[j]  = dw7 [dg * 7  + j];
#pragma unroll
    for (int j = 0; j < 25; j++) w25r[j] = dw25[dg * 25 + j];
#pragma unroll
    for (int j = 0; j < 49; j++) w49r[j] = dw49[dg * 49 + j];
    __syncthreads();

    for (int jo = 0; jo < 16; jo++) {
        int nl = nr + 8 * jo;
        float t7 = 0.f, t25 = 0.f, t49 = 0.f;
#pragma unroll
        for (int j = 0; j < 7; j++)  t7  += w7r[j]  * xs[nl + 21 + j][d];
#pragma unroll
        for (int j = 0; j < 25; j++) t25 += w25r[j] * xs[nl + 12 + j][d];
#pragma unroll
        for (int j = 0; j < 49; j++) t49 += w49r[j] * xs[nl + j][d];
        float tr = w0 * t7 + w1 * t25 + w2 * t49;
        float sv = xs[nl + 24][d] - tr;
        size_t off = ((size_t)(b * NN_SEQ + n0 + nl)) * DD + dg;
        g_Tr[off] = tr;
        g_S [off] = sv;
    }
}

// ---------------- generic LN kernel (nullable f32 + bf16 outputs) -----------
__global__ __launch_bounds__(256) void ln_kernel(
    const float* __restrict__ in, const float* __restrict__ g,
    const float* __restrict__ bta, float* __restrict__ out,
    __nv_bfloat16* __restrict__ out_h)
{
    int bn = blockIdx.x;
    int tid = threadIdx.x;
    const float* row = in + (size_t)bn * DD;
    float v[4]; float sum = 0.f, sumsq = 0.f;
#pragma unroll
    for (int i = 0; i < 4; i++) {
        v[i] = row[tid + i * 256];
        sum += v[i]; sumsq += v[i] * v[i];
    }
    __shared__ float sh1[256], sh2[256];
    sh1[tid] = sum; sh2[tid] = sumsq;
    __syncthreads();
    for (int o = 128; o > 0; o >>= 1) {
        if (tid < o) { sh1[tid] += sh1[tid + o]; sh2[tid] += sh2[tid + o]; }
        __syncthreads();
    }
    float mean = sh1[0] * (1.0f / DD);
    float var  = sh2[0] * (1.0f / DD) - mean * mean;
    float rstd = rsqrtf(var + LN_EPS);
#pragma unroll
    for (int i = 0; i < 4; i++) {
        int d = tid + i * 256;
        float ov = (v[i] - mean) * rstd * g[d] + bta[d];
        if (out)   out[(size_t)bn * DD + d] = ov;
        if (out_h) out_h[(size_t)bn * DD + d] = __float2bfloat16_rn(ov);
    }
}

// ---------------- BF16 tensor-core NT GEMM, ldmatrix + cp.async 3-stage -----
// mode 0: C(f32) = acc + bias (+ addend)
// mode 3: C(f32) = tf32r(acc + bias)
// mode 1: C(bf16)[row] = gelu(acc+bias), A rows gathered via rowidx, row<cnt
// mode 2: C(f32)[rowidx[row]] += (acc + bias) * rowsw[row], row<cnt
__device__ __forceinline__ void mma_bf16(float* d, const uint32_t* a, const uint32_t* b) {
    asm volatile(
        "mma.sync.aligned.m16n8k16.row.col.f32.bf16.bf16.f32 "
        "{%0,%1,%2,%3}, {%4,%5,%6,%7}, {%8,%9}, {%0,%1,%2,%3};"
        : "+f"(d[0]), "+f"(d[1]), "+f"(d[2]), "+f"(d[3])
        : "r"(a[0]), "r"(a[1]), "r"(a[2]), "r"(a[3]),
          "r"(b[0]), "r"(b[1]));
}

__device__ __forceinline__ void ldsm_x4(uint32_t& r0, uint32_t& r1,
                                        uint32_t& r2, uint32_t& r3, uint32_t addr) {
    asm volatile("ldmatrix.sync.aligned.m8n8.x4.shared.b16 {%0,%1,%2,%3}, [%4];"
                 : "=r"(r0), "=r"(r1), "=r"(r2), "=r"(r3) : "r"(addr));
}
__device__ __forceinline__ void ldsm_x2(uint32_t& r0, uint32_t& r1, uint32_t addr) {
    asm volatile("ldmatrix.sync.aligned.m8n8.x2.shared.b16 {%0,%1}, [%2];"
                 : "=r"(r0), "=r"(r1) : "r"(addr));
}

__device__ __forceinline__ void cpa16(float* dst, const void* src) {
    uint32_t d = (uint32_t)__cvta_generic_to_shared(dst);
    asm volatile("cp.async.cg.shared.global [%0], [%1], 16;\n" :: "r"(d), "l"(src));
}

#define GSTG 3
#define GSMEM (GSTG * 4096 * 2 * (int)sizeof(float))   // 96 KB
__global__ __launch_bounds__(256, 2) void gemm_bf16(
    const __nv_bfloat16* __restrict__ A, const __nv_bfloat16* __restrict__ W,
    const float* __restrict__ bias, const float* __restrict__ addend,
    void* __restrict__ Cv, int M, int Nn, int K, int mode,
    const int* __restrict__ rowidx, const int* __restrict__ cnt_ptr,
    const float* __restrict__ rowsw,
    size_t wz, size_t cz, size_t bz, int zr)
{
    int z = blockIdx.z;
    W += (size_t)z * wz;
    if (bias) bias += (size_t)z * bz;
    if (rowidx) rowidx += (size_t)z * zr;
    if (rowsw) rowsw += (size_t)z * zr;
    int cval = cnt_ptr ? cnt_ptr[zr ? z : 0] : M;

    int m0 = blockIdx.y * 128, n0 = blockIdx.x * 128;
    if (m0 >= cval) return;

    extern __shared__ float sm[];
    float* Abuf = sm;
    float* Wbuf = sm + GSTG * 4096;

    int tid = threadIdx.x;
    int lrow = tid >> 1;
    int cbase = (tid & 1) * 4;

    int arow = m0 + lrow;
    if (mode == 1 && rowidx) arow = rowidx[arow < cval ? arow : (cval - 1)];
    const __nv_bfloat16* Aptr = A + (size_t)arow * K + cbase * 8;
    const __nv_bfloat16* Wptr = W + (size_t)(n0 + lrow) * K + cbase * 8;

    int dsts[4];
#pragma unroll
    for (int j = 0; j < 4; j++)
        dsts[j] = lrow * 32 + ((cbase + j) ^ (lrow & 7)) * 4;

    int lane = tid & 31, wid = tid >> 5;
    int wm = wid >> 2, wn = wid & 3;
    int g = lane >> 2, c = lane & 3;

    // ldmatrix per-thread address components (bytes)
    int la = lane & 7;
    int sel8 = (lane >> 3) & 1;
    int hk = (lane >> 4) & 1;
    int arow_off = (wm * 64 + la + 8 * sel8) * 128;
    int brow_off = (wn * 32 + la) * 128;

    float acc[4][4][4];
#pragma unroll
    for (int i = 0; i < 4; i++)
#pragma unroll
        for (int j = 0; j < 4; j++)
#pragma unroll
            for (int r = 0; r < 4; r++) acc[i][j][r] = 0.f;

    int nk = K / 64;
#pragma unroll
    for (int st = 0; st < 2; st++) {
        if (st < nk) {
            int k0 = st * 64;
#pragma unroll
            for (int j = 0; j < 4; j++) {
                cpa16(Abuf + st * 4096 + dsts[j], Aptr + k0 + j * 8);
                cpa16(Wbuf + st * 4096 + dsts[j], Wptr + k0 + j * 8);
            }
            asm volatile("cp.async.commit_group;\n" ::);
        }
    }

    for (int it = 0; it < nk; it++) {
        if (it < nk - 1)
            asm volatile("cp.async.wait_group 1;\n" ::);
        else
            asm volatile("cp.async.wait_group 0;\n" ::);
        __syncthreads();

        int pf = it + 2;
        if (pf < nk) {
            int st = pf % GSTG;
            int k0 = pf * 64;
#pragma unroll
            for (int j = 0; j < 4; j++) {
                cpa16(Abuf + st * 4096 + dsts[j], Aptr + k0 + j * 8);
                cpa16(Wbuf + st * 4096 + dsts[j], Wptr + k0 + j * 8);
            }
            asm volatile("cp.async.commit_group;\n" ::);
        }

        uint32_t AbB = (uint32_t)__cvta_generic_to_shared(Abuf + (it % GSTG) * 4096);
        uint32_t WbB = (uint32_t)__cvta_generic_to_shared(Wbuf + (it % GSTG) * 4096);
#pragma unroll
        for (int s = 0; s < 4; s++) {          // 4 x k16 = 64 k
            int ca = (((2 * s + hk) ^ la) << 4);
            int cb = (((2 * s + sel8) ^ la) << 4);
            uint32_t af[4][4], bf[4][2];
#pragma unroll
            for (int mf = 0; mf < 4; mf++)
                ldsm_x4(af[mf][0], af[mf][1], af[mf][2], af[mf][3],
                        AbB + arow_off + mf * (16 * 128) + ca);
#pragma unroll
            for (int nf = 0; nf < 4; nf++)
                ldsm_x2(bf[nf][0], bf[nf][1],
                        WbB + brow_off + nf * (8 * 128) + cb);
#pragma unroll
            for (int mf = 0; mf < 4; mf++)
#pragma unroll
                for (int nf = 0; nf < 4; nf++)
                    mma_bf16(acc[mf][nf], af[mf], bf[nf]);
        }
    }

    float* C = (float*)Cv + (size_t)z * cz;
    __nv_bfloat16* Cb = (__nv_bfloat16*)Cv + (size_t)z * cz;
#pragma unroll
    for (int mf = 0; mf < 4; mf++) {
#pragma unroll
        for (int half = 0; half < 2; half++) {
            int r = m0 + wm * 64 + mf * 16 + g + half * 8;
#pragma unroll
            for (int nf = 0; nf < 4; nf++) {
                int col = n0 + wn * 32 + nf * 8 + 2 * c;
                float v0 = acc[mf][nf][half * 2 + 0];
                float v1 = acc[mf][nf][half * 2 + 1];
                if (bias) { v0 += bias[col]; v1 += bias[col + 1]; }
                if (mode == 0 || mode == 3) {
                    size_t off = (size_t)r * Nn + col;
                    if (addend) {
                        float2 ad = *(const float2*)&addend[off];
                        v0 += ad.x; v1 += ad.y;
                    }
                    float2 ov = (mode == 3)
                        ? make_float2(tf32r(v0), tf32r(v1))
                        : make_float2(v0, v1);
                    *(float2*)&C[off] = ov;
                } else if (mode == 1) {
                    if (r < cval) {
                        float g0 = 0.5f * v0 * (1.0f + erff(v0 * 0.70710678118f));
                        float g1 = 0.5f * v1 * (1.0f + erff(v1 * 0.70710678118f));
                        __nv_bfloat162 ov = make_bfloat162(
                            __float2bfloat16_rn(g0), __float2bfloat16_rn(g1));
                        *(__nv_bfloat162*)&Cb[(size_t)r * Nn + col] = ov;
                    }
                } else {
                    if (r < cval) {
                        int tok = rowidx[r];
                        float w = rowsw[r];
                        size_t off = (size_t)tok * Nn + col;
                        float2 old = *(const float2*)&C[off];
                        float2 ov = make_float2(old.x + v0 * w, old.y + v1 * w);
                        *(float2*)&C[off] = ov;
                    }
                }
            }
        }
    }
}

// ---------------- attention: TF32 mma flash, 128q x (b,h) per block ---------
#define ATT_SMEM ((4096 + 4096 + 8192) * (int)sizeof(float))
__global__ __launch_bounds__(256) void attn_mma_kernel(
    const float* __restrict__ qkv, __nv_bfloat16* __restrict__ y)
{
    extern __shared__ float sm[];
    float* Ks = sm;
    float* Vt = sm + 4096;
    float* Ps = sm + 8192;

    int bh = blockIdx.x;
    int b = bh >> 4, h = bh & 15;
    int q0 = blockIdx.y * 128;
    int tid = threadIdx.x, lane = tid & 31, wid = tid >> 5;
    int g = lane >> 2, c = lane & 3;
    int qb = wid * 16;
    float slope = exp2f(-0.5f * (float)(h + 1));

    const float* qkvb = qkv + (size_t)(b * NN_SEQ) * (3 * DD);

    for (int i = tid; i < 128 * 16; i += 256) {
        int r = i >> 4, ch = i & 15;
        float4 v = *(const float4*)&qkvb[(size_t)(q0 + r) * (3 * DD) + h * DH + ch * 4];
        *(float4*)&Ps[r * 64 + ((ch ^ (r & 7)) << 2)] = v;
    }
    __syncthreads();

    uint32_t qf[8][4];
#pragma unroll
    for (int s = 0; s < 8; s++) {
        const float* p0 = &Ps[(qb + g) * 64];
        const float* p1 = &Ps[(qb + 8 + g) * 64];
        int sw0 = (((2 * s) ^ g) << 2) + c;
        int sw1 = (((2 * s + 1) ^ g) << 2) + c;
        qf[s][0] = __float_as_uint(p0[sw0] * 0.125f);
        qf[s][1] = __float_as_uint(p1[sw0] * 0.125f);
        qf[s][2] = __float_as_uint(p0[sw1] * 0.125f);
        qf[s][3] = __float_as_uint(p1[sw1] * 0.125f);
    }

    float oa[8][4];
#pragma unroll
    for (int i = 0; i < 8; i++)
#pragma unroll
        for (int j = 0; j < 4; j++) oa[i][j] = 0.f;
    float m_lo = -1e30f, m_hi = -1e30f, l_lo = 0.f, l_hi = 0.f;
    int qlo = q0 + qb + g, qhi = qlo + 8;

    for (int kt = 0; kt < NN_SEQ; kt += 64) {
        __syncthreads();
        for (int i = tid; i < 64 * 16; i += 256) {
            int r = i >> 4, ch = i & 15;
            size_t rowoff = (size_t)(kt + r) * (3 * DD) + h * DH + ch * 4;
            int dst = r * 64 + ((ch ^ (r & 7)) << 2);
            *(float4*)&Ks[dst] = *(const float4*)&qkvb[DD + rowoff];
            *(float4*)&Ps[dst] = *(const float4*)&qkvb[2 * DD + rowoff];
        }
        __syncthreads();

        {
            int d = tid & 63, kg = tid >> 6;
#pragma unroll
            for (int i = 0; i < 16; i++) {
                int kk = kg * 16 + i;
                float v = Ps[kk * 64 + (((d >> 2) ^ (kk & 7)) << 2) + (d & 3)];
                Vt[d * 64 + (((kk >> 2) ^ (d & 7)) << 2) + (kk & 3)] = v;
            }
        }

        float sa[8][4];
#pragma unroll
        for (int i = 0; i < 8; i++)
#pragma unroll
            for (int j = 0; j < 4; j++) sa[i][j] = 0.f;
#pragma unroll
        for (int s = 0; s < 8; s++) {
            int sw0 = (((2 * s) ^ g) << 2) + c;
            int sw1 = (((2 * s + 1) ^ g) << 2) + c;
#pragma unroll
            for (int nt = 0; nt < 8; nt++) {
                const float* pk = &Ks[(nt * 8 + g) * 64];
                uint32_t bfr[2];
                bfr[0] = __float_as_uint(pk[sw0]);
                bfr[1] = __float_as_uint(pk[sw1]);
                asm volatile(
                    "mma.sync.aligned.m16n8k8.row.col.f32.tf32.tf32.f32 "
                    "{%0,%1,%2,%3}, {%4,%5,%6,%7}, {%8,%9}, {%0,%1,%2,%3};"
                    : "+f"(sa[nt][0]), "+f"(sa[nt][1]), "+f"(sa[nt][2]), "+f"(sa[nt][3])
                    : "r"(qf[s][0]), "r"(qf[s][1]), "r"(qf[s][2]), "r"(qf[s][3]),
                      "r"(bfr[0]), "r"(bfr[1]));
            }
        }
        __syncthreads();

        float mx_lo = -1e30f, mx_hi = -1e30f;
#pragma unroll
        for (int nt = 0; nt < 8; nt++) {
            int k0 = kt + nt * 8 + 2 * c;
            float d0 = (k0 > qlo) ? (float)(k0 - qlo) : 0.f;
            float d1 = (k0 + 1 > qlo) ? (float)(k0 + 1 - qlo) : 0.f;
            float d2 = (k0 > qhi) ? (float)(k0 - qhi) : 0.f;
            float d3 = (k0 + 1 > qhi) ? (float)(k0 + 1 - qhi) : 0.f;
            sa[nt][0] -= slope * d0; sa[nt][1] -= slope * d1;
            sa[nt][2] -= slope * d2; sa[nt][3] -= slope * d3;
            mx_lo = fmaxf(mx_lo, fmaxf(sa[nt][0], sa[nt][1]));
            mx_hi = fmaxf(mx_hi, fmaxf(sa[nt][2], sa[nt][3]));
        }
        mx_lo = fmaxf(mx_lo, __shfl_xor_sync(0xffffffffu, mx_lo, 1));
        mx_lo = fmaxf(mx_lo, __shfl_xor_sync(0xffffffffu, mx_lo, 2));
        mx_hi = fmaxf(mx_hi, __shfl_xor_sync(0xffffffffu, mx_hi, 1));
        mx_hi = fmaxf(mx_hi, __shfl_xor_sync(0xffffffffu, mx_hi, 2));
        float mn_lo = fmaxf(m_lo, mx_lo), mn_hi = fmaxf(m_hi, mx_hi);
        float cc_lo = __expf(m_lo - mn_lo), cc_hi = __expf(m_hi - mn_hi);
        m_lo = mn_lo; m_hi = mn_hi;

        float rs_lo = 0.f, rs_hi = 0.f;
#pragma unroll
        for (int nt = 0; nt < 8; nt++) {
            float p0 = __expf(sa[nt][0] - mn_lo), p1 = __expf(sa[nt][1] - mn_lo);
            float p2 = __expf(sa[nt][2] - mn_hi), p3 = __expf(sa[nt][3] - mn_hi);
            rs_lo += p0 + p1; rs_hi += p2 + p3;
            int col = nt * 8 + 2 * c;
            int ch = col >> 2, off = col & 3;
            *(float2*)&Ps[(qb + g) * 64 + ((ch ^ g) << 2) + off] =
                make_float2(tf32r(p0), tf32r(p1));
            *(float2*)&Ps[(qb + 8 + g) * 64 + ((ch ^ g) << 2) + off] =
                make_float2(tf32r(p2), tf32r(p3));
        }
        rs_lo += __shfl_xor_sync(0xffffffffu, rs_lo, 1);
        rs_lo += __shfl_xor_sync(0xffffffffu, rs_lo, 2);
        rs_hi += __shfl_xor_sync(0xffffffffu, rs_hi, 1);
        rs_hi += __shfl_xor_sync(0xffffffffu, rs_hi, 2);
        l_lo = l_lo * cc_lo + rs_lo;
        l_hi = l_hi * cc_hi + rs_hi;
#pragma unroll
        for (int nt = 0; nt < 8; nt++) {
            oa[nt][0] *= cc_lo; oa[nt][1] *= cc_lo;
            oa[nt][2] *= cc_hi; oa[nt][3] *= cc_hi;
        }
        __syncwarp();

#pragma unroll
        for (int s2 = 0; s2 < 8; s2++) {
            int sw0 = (((2 * s2) ^ g) << 2) + c;
            int sw1 = (((2 * s2 + 1) ^ g) << 2) + c;
            const float* pl = &Ps[(qb + g) * 64];
            const float* ph = &Ps[(qb + 8 + g) * 64];
            uint32_t af[4];
            af[0] = __float_as_uint(pl[sw0]);
            af[1] = __float_as_uint(ph[sw0]);
            af[2] = __float_as_uint(pl[sw1]);
            af[3] = __float_as_uint(ph[sw1]);
#pragma unroll
            for (int nt = 0; nt < 8; nt++) {
                const float* pv = &Vt[(nt * 8 + g) * 64];
                uint32_t bfr[2];
                bfr[0] = __float_as_uint(pv[sw0]);
                bfr[1] = __float_as_uint(pv[sw1]);
                asm volatile(
                    "mma.sync.aligned.m16n8k8.row.col.f32.tf32.tf32.f32 "
                    "{%0,%1,%2,%3}, {%4,%5,%6,%7}, {%8,%9}, {%0,%1,%2,%3};"
                    : "+f"(oa[nt][0]), "+f"(oa[nt][1]), "+f"(oa[nt][2]), "+f"(oa[nt][3])
                    : "r"(af[0]), "r"(af[1]), "r"(af[2]), "r"(af[3]),
                      "r"(bfr[0]), "r"(bfr[1]));
            }
        }
    }

    float il_lo = 1.0f / l_lo, il_hi = 1.0f / l_hi;
#pragma unroll
    for (int nt = 0; nt < 8; nt++) {
        int col = h * DH + nt * 8 + 2 * c;
        size_t rlo = (size_t)(b * NN_SEQ + qlo) * DD + col;
        __nv_bfloat162 o0 = make_bfloat162(
            __float2bfloat16_rn(oa[nt][0] * il_lo),
            __float2bfloat16_rn(oa[nt][1] * il_lo));
        __nv_bfloat162 o1 = make_bfloat162(
            __float2bfloat16_rn(oa[nt][2] * il_hi),
            __float2bfloat16_rn(oa[nt][3] * il_hi));
        *(__nv_bfloat162*)&y[rlo] = o0;
        *(__nv_bfloat162*)&y[rlo + 8 * DD] = o1;
    }
}

// ---------------- router: gates + top-2 weights -----------------------------
__global__ __launch_bounds__(128) void router_kernel(
    const float* __restrict__ xf, const float* __restrict__ rw)
{
    int t = blockIdx.x;
    int lane = threadIdx.x & 31, wrp = threadIdx.x >> 5;
    const float* xr = xf + (size_t)t * DD;
    const float* wr = rw + (size_t)wrp * DD;
    float s = 0.f;
    for (int i = lane; i < DD; i += 32) s += xr[i] * wr[i];
#pragma unroll
    for (int o = 16; o > 0; o >>= 1) s += __shfl_xor_sync(0xffffffffu, s, o);
    __shared__ float sh[4];
    if (lane == 0) sh[wrp] = s;
    __syncthreads();
    if (threadIdx.x == 0) {
        float g[4]; float mx = -1e30f;
#pragma unroll
        for (int e = 0; e < EE; e++) { g[e] = sh[e]; mx = fmaxf(mx, g[e]); }
        float sum = 0.f;
#pragma unroll
        for (int e = 0; e < EE; e++) { g[e] = __expf(g[e] - mx); sum += g[e]; }
        float inv = 1.0f / sum;
#pragma unroll
        for (int e = 0; e < EE; e++) { g[e] *= inv; g_gates[t * EE + e] = g[e]; }
        int i1 = 0;
#pragma unroll
        for (int e = 1; e < EE; e++) if (g[e] > g[i1]) i1 = e;
        int i2 = -1;
#pragma unroll
        for (int e = 0; e < EE; e++)
            if (e != i1 && (i2 < 0 || g[e] > g[i2])) i2 = e;
        float norm = fmaxf(g[i1] + g[i2], 1e-9f);
        float w4[4] = {0.f, 0.f, 0.f, 0.f};
        w4[i1] = g[i1] / norm;
        w4[i2] = g[i2] / norm;
#pragma unroll
        for (int e = 0; e < EE; e++) g_wts[t * EE + e] = w4[e];
    }
}

// ---------------- expert token lists ----------------------------------------
__global__ void clear_cnt_kernel() {
    if (threadIdx.x < EE) g_cnt[threadIdx.x] = 0;
}

__global__ __launch_bounds__(256) void build_lists_kernel() {
    int t = blockIdx.x * 256 + threadIdx.x;
    if (t >= TT) return;
#pragma unroll
    for (int e = 0; e < EE; e++) {
        float w = g_wts[t * EE + e];
        if (w > 0.f) {
            int p = atomicAdd(&g_cnt[e], 1);
            g_list[e * TT + p] = t;
            g_lw[e * TT + p] = w;
        }
    }
}

// ---------------- deterministic aux reduction -------------------------------
__global__ __launch_bounds__(256) void aux_reduce_kernel()
{
    int tid = threadIdx.x;
    float sg[EE] = {0.f, 0.f, 0.f, 0.f};
    float sc[EE] = {0.f, 0.f, 0.f, 0.f};
    for (int t = tid; t < TT; t += 256) {
#pragma unroll
        for (int e = 0; e < EE; e++) {
            sg[e] += g_gates[t * EE + e];
            sc[e] += (g_wts[t * EE + e] > 0.f) ? 1.f : 0.f;
        }
    }
    __shared__ float sh[256];
    float aux = 0.f;
#pragma unroll
    for (int e = 0; e < EE; e++) {
        sh[tid] = sg[e]; __syncthreads();
        for (int o = 128; o > 0; o >>= 1) {
            if (tid < o) sh[tid] += sh[tid + o];
            __syncthreads();
        }
        float tot_g = sh[0]; __syncthreads();
        sh[tid] = sc[e]; __syncthreads();
        for (int o = 128; o > 0; o >>= 1) {
            if (tid < o) sh[tid] += sh[tid + o];
            __syncthreads();
        }
        float tot_c = sh[0]; __syncthreads();
        aux += (tot_g / (float)TT) * (tot_c / (float)TT);
    }
    if (tid == 0) g_auxval[0] = (float)EE * aux;
}

// ---------------- final: + trend depthwise conv(k=5) + aux ------------------
__global__ __launch_bounds__(256) void final_kernel(
    const float* __restrict__ tw, const float* __restrict__ tb,
    float* __restrict__ out, int write_aux)
{
    int bn = blockIdx.x;
    int b = bn / NN_SEQ, n = bn % NN_SEQ;
    int tid = threadIdx.x;
#pragma unroll
    for (int i = 0; i < 4; i++) {
        int d = tid + i * 256;
        float vsum = g_xs[(size_t)bn * DD + d] + tb[d];
#pragma unroll
        for (int j = 0; j < 5; j++) {
            int nn = n - 2 + j;
            if (nn >= 0 && nn < NN_SEQ)
                vsum += tw[d * 5 + j] * g_Tr[((size_t)b * NN_SEQ + nn) * DD + d];
        }
        out[(size_t)bn * DD + d] = vsum;
    }
    if (bn == 0 && tid == 0 && write_aux)
        out[(size_t)BB * NN_SEQ * DD] = g_auxval[0];
}

// ---------------- host orchestration ---------------------------------------
extern "C" void kernel_launch(void* const* d_in, const int* in_sizes, int n_in,
                              void* d_out, int out_size)
{
    const float* x    = (const float*)d_in[0];
    const float* qw   = (const float*)d_in[1];
    const float* qb   = (const float*)d_in[2];
    const float* kw   = (const float*)d_in[3];
    const float* kb   = (const float*)d_in[4];
    const float* vw   = (const float*)d_in[5];
    const float* vb   = (const float*)d_in[6];
    const float* ow   = (const float*)d_in[7];
    const float* ob   = (const float*)d_in[8];
    const float* n1g  = (const float*)d_in[9];
    const float* n1b  = (const float*)d_in[10];
    const float* n2g  = (const float*)d_in[11];
    const float* n2b  = (const float*)d_in[12];
    const float* alpha= (const float*)d_in[13];
    const float* dw7  = (const float*)d_in[14];
    const float* dw25 = (const float*)d_in[15];
    const float* dw49 = (const float*)d_in[16];
    const float* rw   = (const float*)d_in[17];
    const float* ew1  = (const float*)d_in[18];
    const float* eb1  = (const float*)d_in[19];
    const float* ew2  = (const float*)d_in[20];
    const float* eb2  = (const float*)d_in[21];
    const float* tw   = (const float*)d_in[22];
    const float* tb   = (const float*)d_in[23];
    float* out = (float*)d_out;

    float *p_qkv, *p_xs, *p_xf, *p_S, *p_lw, *p_qkvb;
    __nv_bfloat16 *p_Snh, *p_yh, *p_xfh, *p_hh, *p_wh;
    int *p_list, *p_cnt;
    cudaGetSymbolAddress((void**)&p_Snh, g_Snh);
    cudaGetSymbolAddress((void**)&p_qkv, g_qkv);
    cudaGetSymbolAddress((void**)&p_yh,  g_yh);
    cudaGetSymbolAddress((void**)&p_xs, g_xs);
    cudaGetSymbolAddress((void**)&p_xf, g_xf);
    cudaGetSymbolAddress((void**)&p_xfh, g_xfh);
    cudaGetSymbolAddress((void**)&p_hh,  g_hh);
    cudaGetSymbolAddress((void**)&p_S,  g_S);
    cudaGetSymbolAddress((void**)&p_lw,  g_lw);
    cudaGetSymbolAddress((void**)&p_list, g_list);
    cudaGetSymbolAddress((void**)&p_cnt,  g_cnt);
    cudaGetSymbolAddress((void**)&p_wh,  g_wh);
    cudaGetSymbolAddress((void**)&p_qkvb, g_qkvb);

    cudaFuncSetAttribute(attn_mma_kernel,
                         cudaFuncAttributeMaxDynamicSharedMemorySize, ATT_SMEM);
    cudaFuncSetAttribute(gemm_bf16,
                         cudaFuncAttributeMaxDynamicSharedMemorySize, GSMEM);

    // launches ordered so #6 (0-based 5) is the QKV GEMM for ncu -s 5 -c 1
    // 1) decomposition
    decomp_kernel<<<dim3(DD / 32, NN_SEQ / DNT, BB), 256>>>(
        x, alpha, dw7, dw25, dw49);
    // 2) LN1 -> Snh (bf16)
    ln_kernel<<<BB * NN_SEQ, 256>>>(p_S, n1g, n1b, nullptr, p_Snh);
    // 3) concat QKV biases
    concat_bias_kernel<<<(DD + 255) / 256, 256>>>(qb, kb, vb);
    // 4) round q/k/v weights (merged)
    round_bf16_3_kernel<<<(3 * DD * DD) / 4096, 256>>>(qw, kw, vw, p_wh + WR_Q, DD * DD);
    // 5) round o weights
    round_bf16_kernel<<<(DD * DD) / 4096, 256>>>(ow, p_wh + WR_O, DD * DD);
    // 6) fused QKV projection (bf16, ldmatrix) -> g_qkv f32 tf32-rounded
    gemm_bf16<<<dim3(3 * DD / 128, TT / 128), 256, GSMEM>>>(
        p_Snh, p_wh + WR_Q, p_qkvb, nullptr, p_qkv, TT, 3 * DD, DD, 3,
        nullptr, nullptr, nullptr, 0, 0, 0, 0);

    // 7) ALiBi attention (tf32 mma) -> y bf16
    attn_mma_kernel<<<dim3(BB * HH, NN_SEQ / 128), 256, ATT_SMEM>>>(p_qkv, p_yh);

    // 8) round expert weights (merged, contiguous dst)
    round_bf16_2_kernel<<<(2 * EE * MH * DD) / 4096, 256>>>(
        ew1, ew2, p_wh + WR_E1, EE * MH * DD);

    // 9) output projection + residual: x_s = S + (y @ ow^T + ob)
    dim3 gQ(DD / 128, TT / 128);
    gemm_bf16<<<gQ, 256, GSMEM>>>(p_yh, p_wh + WR_O, ob, p_S, p_xs, TT, DD, DD, 0,
                                  nullptr, nullptr, nullptr, 0, 0, 0, 0);

    // 10) LN2 -> xf (exact f32) + xfh (bf16)
    ln_kernel<<<BB * NN_SEQ, 256>>>(p_xs, n2g, n2b, p_xf, p_xfh);

    // 11-14) router, token lists, aux
    router_kernel<<<TT, 128>>>(p_xf, rw);
    clear_cnt_kernel<<<1, 32>>>();
    build_lists_kernel<<<TT / 256, 256>>>();
    aux_reduce_kernel<<<1, 256>>>();

    // 15) batched MoE GEMM1 over all experts (z = expert)
    gemm_bf16<<<dim3(MH / 128, TT / 128, EE), 256, GSMEM>>>(
        p_xfh, p_wh + WR_E1, eb1, nullptr, p_hh, TT, MH, DD, 1,
        p_list, p_cnt, nullptr,
        (size_t)MH * DD, (size_t)TT * MH, (size_t)MH, TT);

    // 16-19) MoE GEMM2 scatter-accumulate (sequential: in-place RMW on xs)
    dim3 gE2(DD / 128, TT / 128);
    for (int e = 0; e < EE; e++) {
        gemm_bf16<<<gE2, 256, GSMEM>>>(
            p_hh + (size_t)e * TT * MH, p_wh + WR_E2 + (size_t)e * DD * MH,
            eb2 + (size_t)e * DD, nullptr, p_xs, TT, DD, MH, 2,
            p_list + e * TT, p_cnt + e, p_lw + e * TT, 0, 0, 0, 0);
    }

    // 20) trend conv + final sum + aux scalar
    int write_aux = (out_size > BB * NN_SEQ * DD) ? 1 : 0;
    final_kernel<<<BB * NN_SEQ, 256>>>(tw, tb, out, write_aux);
}